// round 13
// baseline (speedup 1.0000x reference)
#include <cuda_runtime.h>
#include <cuda_fp16.h>
#include <math.h>

// ---------------- problem constants ----------------
#define NN    4096
#define KNNK  20
#define LRKK  40
#define EPN   60
#define LL    9
#define SPH   35
#define BBC   32
#define NBB   3
#define HEADS 8
#define HV    64
#define HC    32
#define EPB   64
#define NVB   8
#define CAP   3072
#define VSTR  320          // per-node v stride in half2 words (5 planes x 64)

#define OFF_BB  (NN*3)
#define OFF_OUT (NN*3 + NN*9)

__device__ int     g_src[NN*EPN];
__device__ float   g_logit[NN*EPN*HEADS];
__device__ float   g_inv[NN*SPH];
__device__ __half2 g_vp[NN*VSTR];   // plane-major: [node][k(0..4)][d(0..63)]
__device__ float   g_hsrc[NN*HC];
__device__ float   g_hdst[NN*HC];
__device__ float4  g_xp[NN];        // [x,y,z,x2]; x2=+inf if x_mask

__constant__ int c_L3[LL] = {0,1,1,1,2,2,2,2,2};

// ---------------- threefry2x32 lr key (JAX partitionable path) --------------
__device__ __forceinline__ float lr_key(unsigned int idx, float d2e) {
    unsigned int x0 = 0u, x1 = idx;
    const unsigned int ks0 = 0u, ks1 = 1u, ks2 = 0x1BD11BDBu;
    x0 += ks0; x1 += ks1;
#define TFR(r) { x0 += x1; x1 = __funnelshift_l(x1, x1, (r)); x1 ^= x0; }
    TFR(13) TFR(15) TFR(26) TFR(6);  x0 += ks1; x1 += ks2 + 1u;
    TFR(17) TFR(29) TFR(16) TFR(24); x0 += ks2; x1 += ks0 + 2u;
    TFR(13) TFR(15) TFR(26) TFR(6);  x0 += ks0; x1 += ks1 + 3u;
    TFR(17) TFR(29) TFR(16) TFR(24); x0 += ks1; x1 += ks2 + 4u;
    TFR(13) TFR(15) TFR(26) TFR(6);  x0 += ks2; x1 += ks0 + 5u;
#undef TFR
    unsigned int bits = x0 ^ x1;
    float u = __uint_as_float((bits >> 9) | 0x3f800000u) - 1.0f;
    u = fmaxf(u, 1.17549435e-38f);
    float w = -__logf(u);
    return w * (d2e * __fsqrt_rn(d2e));
}

// ---------------- kernel 1: node features + V(fp16 plane-major) + partials --
__global__ __launch_bounds__(512) void node_v_kernel(
    const float* __restrict__ bbf, const float* __restrict__ bbr,
    const int* __restrict__ noise, const int* __restrict__ xmask,
    const float* __restrict__ X,
    const float* __restrict__ wv, const float* __restrict__ bv,
    const float* __restrict__ w1, const float* __restrict__ b1)
{
    __shared__ float sWV[3*SPH*HV];
    __shared__ float sW1[2*SPH*HC];
    __shared__ float nf[NVB][LL*SPH];
    const int t = threadIdx.x;
    for (int idx = t; idx < 3*SPH*HV; idx += 512) sWV[idx] = wv[idx];
    for (int idx = t; idx < 2*SPH*HC; idx += 512) sW1[idx] = w1[idx];

    const int g = t >> 6;
    const int tt = t & 63;
    const int i = blockIdx.x*NVB + g;

    for (int idx = tt; idx < LL*SPH; idx += 64) {
        int l = idx / SPH, c = idx - l*SPH;
        float v = 0.f;
        if (c < BBC)                    v = bbf[(i*LL + l)*BBC + c];
        else if (l >= 1 && l <= 3)      v = bbr[(i*NBB + (c-BBC))*3 + (l-1)];
        if (l == 0 && c == SPH-1)       v = noise[i] ? 1.0f : 0.0f;
        nf[g][idx] = v;
    }
    if (tt == 0) {
        float x = X[3*i], y = X[3*i+1], z = X[3*i+2];
        float x2 = __fadd_rn(__fadd_rn(__fmul_rn(x,x),__fmul_rn(y,y)),__fmul_rn(z,z));
        g_xp[i] = make_float4(x, y, z, xmask[i] ? __int_as_float(0x7F800000) : x2);
    }
    __syncthreads();
    if (tt < SPH) g_inv[i*SPH + tt] = nf[g][tt];

    if (tt < HC) {
        float acc = b1[tt];
#pragma unroll 7
        for (int c = 0; c < SPH; ++c) acc = __fmaf_rn(nf[g][c], sW1[c*HC + tt], acc);
        g_hsrc[i*HC + tt] = acc;
    } else {
        int d = tt - HC;
        float acc = 0.f;
#pragma unroll 7
        for (int c = 0; c < SPH; ++c) acc = __fmaf_rn(nf[g][c], sW1[(SPH + c)*HC + d], acc);
        g_hdst[i*HC + d] = acc;
    }

    {
        const int d = tt;
        float va[LL];
#pragma unroll
        for (int l = 0; l < LL; ++l) {
            const float* w = sWV + c_L3[l]*SPH*HV;
            float acc = 0.f;
#pragma unroll 7
            for (int c = 0; c < SPH; ++c) acc = __fmaf_rn(nf[g][l*SPH + c], w[c*HV + d], acc);
            if (l == 0) acc += bv[d];
            va[l] = acc;
        }
        __half2* dst = g_vp + (size_t)i*VSTR + d;   // plane-major, coalesced
        dst[0]   = __floats2half2_rn(va[0], va[1]);
        dst[64]  = __floats2half2_rn(va[2], va[3]);
        dst[128] = __floats2half2_rn(va[4], va[5]);
        dst[192] = __floats2half2_rn(va[6], va[7]);
        dst[256] = __floats2half2_rn(va[8], 0.f);
    }
}

// ---------------- radix-select with candidate compaction --------------------
#define PICK(BYTE)                                                             \
    {                                                                          \
        unsigned cnt = 0;                                                      \
        _Pragma("unroll")                                                      \
        for (int c = 0; c < 8; ++c) cnt += hist[c][t];                         \
        unsigned v = cnt;                                                      \
        _Pragma("unroll")                                                      \
        for (int o = 1; o < 32; o <<= 1) {                                     \
            unsigned n = __shfl_up_sync(0xffffffffu, v, o);                    \
            if (lane >= o) v += n;                                             \
        }                                                                      \
        if (lane == 31) sScan[w] = v;                                          \
        __syncthreads();                                                       \
        if (t == 0) {                                                          \
            unsigned a = 0;                                                    \
            _Pragma("unroll")                                                  \
            for (int c = 0; c < 8; ++c) { unsigned x = sScan[c]; sScan[c] = a; a += x; } \
        }                                                                      \
        __syncthreads();                                                       \
        unsigned incl = v + sScan[w];                                          \
        unsigned excl = incl - cnt;                                            \
        if (kk > excl && kk <= incl) { sScan[8] = (unsigned)t; sScan[9] = excl; } \
        __syncthreads();                                                       \
        prefix |= sScan[8] << (8*(BYTE));                                      \
        kk -= sScan[9];                                                        \
        __syncthreads();                                                       \
    }

__device__ __forceinline__ uint2 radix_select(
    const unsigned* s_key, unsigned (*hist)[256], unsigned* sScan,
    unsigned short* cand, unsigned* sCnt,
    unsigned k, unsigned validMax, int t)
{
    const int lane = t & 31, w = t >> 5;
    unsigned prefix = 0, kk = k;

    PICK(3)

    if (t == 0) sCnt[0] = 0;
    __syncthreads();
    const unsigned b3 = prefix >> 24;
    for (int j = t; j < NN; j += 256) {
        unsigned u = s_key[j];
        if (u < validMax && (u >> 24) == b3) {
            unsigned p = atomicAdd(&sCnt[0], 1u);
            if (p < CAP) cand[p] = (unsigned short)j;
        }
    }
    __syncthreads();
    const int candN = (int)sCnt[0];
    const bool useCand = (candN <= CAP);

#pragma unroll
    for (int byte = 2; byte >= 0; --byte) {
        const unsigned maskHi = 0xFFFFFFFFu << (8*(byte+1));
#pragma unroll
        for (int c = 0; c < 8; ++c) hist[c][t] = 0;
        __syncthreads();
        if (useCand) {
            for (int c = t; c < candN; c += 256) {
                unsigned u = s_key[cand[c]];
                if ((u & maskHi) == prefix)
                    atomicAdd(&hist[w][(u >> (8*byte)) & 255u], 1u);
            }
        } else {
            for (int j = t; j < NN; j += 256) {
                unsigned u = s_key[j];
                if (u < validMax && (u & maskHi) == prefix)
                    atomicAdd(&hist[w][(u >> (8*byte)) & 255u], 1u);
            }
        }
        __syncthreads();
        PICK(byte)
    }
    return make_uint2(prefix, kk);
}

// ---------------- kernel 2: distances + knn top20 + lr top40 ---------------
__global__ __launch_bounds__(256) void row_kernel(
    const int* __restrict__ xmask)
{
    __shared__ unsigned s_key[NN];
    __shared__ unsigned s_hist[8][256];
    __shared__ unsigned sScan[10];
    __shared__ unsigned short sCand[CAP];
    __shared__ unsigned sCnt[4];
    __shared__ int      sSel[EPN];
    __shared__ int      sTie[64];
    const int i = blockIdx.x;
    const int t = threadIdx.x;
    const int w = t >> 5;
    const unsigned U_INV = __float_as_uint(1e30f);

    if (xmask[i] != 0) {
        for (int e = t; e < EPN; e += 256)
            g_src[i*EPN + e] = (e < KNNK) ? e : (e - KNNK);
        return;
    }

    const float4 pi = g_xp[i];
    const float xi = pi.x, yi = pi.y, zi = pi.z, x2i = pi.w;
    const int bi = i >> 11;

#pragma unroll
    for (int c = 0; c < 8; ++c) s_hist[c][t] = 0;
    __syncthreads();
    for (int j = t; j < NN; j += 256) {
        float4 p = g_xp[j];
        float dot = __fmul_rn(xi, p.x);
        dot = __fmaf_rn(yi, p.y, dot);
        dot = __fmaf_rn(zi, p.z, dot);
        float d2  = fmaxf(__fsub_rn(__fadd_rn(x2i, p.w), __fmul_rn(2.0f, dot)), 0.0f);
        bool invalid = ((j >> 11) != bi) || (j == i);
        unsigned u = invalid ? U_INV : __float_as_uint(d2);
        s_key[j] = u;
        if (u < U_INV) atomicAdd(&s_hist[w][u >> 24], 1u);
    }
    __syncthreads();

    // ================= knn stage =================
    {
        uint2 rk = radix_select(s_key, s_hist, sScan, sCand, sCnt, KNNK, U_INV, t);
        const unsigned T = rk.x;
        const int need = (int)rk.y;
        const int cLess = KNNK - need;

        if (t == 0) { sCnt[1] = 0; sCnt[2] = 0; }
        __syncthreads();
        for (int j = t; j < NN; j += 256) {
            unsigned u = s_key[j];
            if (u < T) {
                int p = (int)atomicAdd(&sCnt[1], 1u);
                sSel[p] = j;
            } else if (u == T) {
                int p = (int)atomicAdd(&sCnt[2], 1u);
                if (p < 64) sTie[p] = j;
            }
        }
        __syncthreads();
        if (t == 0) {
            int nt = min((int)sCnt[2], 64);
            int last = -1;
            for (int r = 0; r < need; ++r) {
                int best = 0x7FFFFFFF;
                for (int q = 0; q < nt; ++q) { int j = sTie[q]; if (j > last && j < best) best = j; }
                sSel[cLess + r] = best;
                last = best;
            }
        }
        __syncthreads();
        if (t < KNNK) {
            int myj = sSel[t];
            int rank = 0;
#pragma unroll 4
            for (int q = 0; q < KNNK; ++q) rank += (sSel[q] < myj);
            g_src[i*EPN + rank] = myj;
            s_key[myj] = U_INV;
        }
        __syncthreads();
    }

#pragma unroll
    for (int c = 0; c < 8; ++c) s_hist[c][t] = 0;
    __syncthreads();
    for (int j = t; j < NN; j += 256) {
        unsigned u = s_key[j];
        unsigned outk = U_INV;
        if (u < U_INV) {
            float d2e = __fadd_rn(__uint_as_float(u), 1e-6f);
            float s = lr_key((unsigned)(i*NN + j), d2e);
            outk = __float_as_uint(s);
            atomicAdd(&s_hist[w][outk >> 24], 1u);
        }
        s_key[j] = outk;
    }
    __syncthreads();

    // ================= lr stage =================
    {
        uint2 rk = radix_select(s_key, s_hist, sScan, sCand, sCnt, LRKK, U_INV, t);
        const unsigned T = rk.x;
        const int need = (int)rk.y;
        const int cLess = LRKK - need;

        if (t == 0) { sCnt[1] = 0; sCnt[2] = 0; }
        __syncthreads();
        for (int j = t; j < NN; j += 256) {
            unsigned u = s_key[j];
            if (u < T) {
                int p = (int)atomicAdd(&sCnt[1], 1u);
                sSel[p] = j;
            } else if (u == T) {
                int p = (int)atomicAdd(&sCnt[2], 1u);
                if (p < 64) sTie[p] = j;
            }
        }
        __syncthreads();
        if (t == 0) {
            int nt = min((int)sCnt[2], 64);
            int last = -1;
            for (int r = 0; r < need; ++r) {
                int best = 0x7FFFFFFF;
                for (int q = 0; q < nt; ++q) { int j = sTie[q]; if (j > last && j < best) best = j; }
                sSel[cLess + r] = best;
                last = best;
            }
        }
        __syncthreads();
        if (t < LRKK) {
            int myj = sSel[t];
            int rank = 0;
#pragma unroll 4
            for (int q = 0; q < LRKK; ++q) rank += (sSel[q] < myj);
            g_src[i*EPN + KNNK + rank] = myj;
        }
    }
}

// ---------------- kernel 3: edge MLP (factorized; 8 edges per warp) ---------
__global__ __launch_bounds__(256) void edge_kernel(
    const float* __restrict__ w1,
    const float* __restrict__ w2, const float* __restrict__ b2)
{
    __shared__ float sW1eT[HC][36];
    __shared__ float sW2T[HEADS][36];
    __shared__ float sB2[HEADS];
    __shared__ float sEF[8][8][40];
    __shared__ float sH[8][8][40];
    const int t = threadIdx.x, lane = t & 31, warp = t >> 5;
    for (int idx = t; idx < HC*32; idx += 256) {
        int h = idx >> 5, c = idx & 31;
        sW1eT[h][c] = w1[(2*SPH + c)*HC + h];
    }
    for (int idx = t; idx < HEADS*32; idx += 256) {
        int h = idx >> 5, c = idx & 31;
        sW2T[h][c] = w2[c*HEADS + h];
    }
    if (t < HEADS) sB2[t] = b2[t];
    __syncthreads();

    const int e0 = blockIdx.x*EPB + warp*8;

    {
        const int e = lane >> 2, q = lane & 3;
        const int edge = e0 + e;
        const int ii = edge / EPN;
        const int ss = g_src[edge];
        float4 ps = g_xp[ss], pd = g_xp[ii];
        float dx = ps.x-pd.x, dy = ps.y-pd.y, dz = ps.z-pd.z;
        float dist = sqrtf(__fadd_rn(__fadd_rn(__fmul_rn(dx,dx),__fmul_rn(dy,dy)),__fmul_rn(dz,dz)));
        if (q < 2) {
#pragma unroll
            for (int r = 0; r < 8; ++r) {
                int f = q*8 + r;
                float mu = (float)f * (20.0f/15.0f);
                float zz = (dist - mu) * 0.8f;
                sEF[warp][e][f] = expf(-zz*zz);
            }
        } else {
            float dfl = (float)(ss - ii);
#pragma unroll
            for (int r = 0; r < 4; ++r) {
                int k = (q-2)*4 + r;
                float fr = expf((float)(2*k) * -0.5756462732485114f);
                float sv, cv;
                sincosf(dfl * fr, &sv, &cv);
                sEF[warp][e][16 + k] = cv;
                sEF[warp][e][24 + k] = sv;
            }
        }
    }
    __syncwarp();

    {
        float h[8];
#pragma unroll
        for (int e = 0; e < 8; ++e) {
            const int edge = e0 + e;
            const int ii = edge / EPN;
            const int ss = g_src[edge];
            h[e] = g_hsrc[ss*HC + lane] + g_hdst[ii*HC + lane];
        }
#pragma unroll
        for (int c4 = 0; c4 < 32; c4 += 4) {
            float4 w4 = *(const float4*)&sW1eT[lane][c4];
#pragma unroll
            for (int e = 0; e < 8; ++e) {
                float4 f4 = *(const float4*)&sEF[warp][e][c4];
                h[e] = __fmaf_rn(f4.x, w4.x, h[e]);
                h[e] = __fmaf_rn(f4.y, w4.y, h[e]);
                h[e] = __fmaf_rn(f4.z, w4.z, h[e]);
                h[e] = __fmaf_rn(f4.w, w4.w, h[e]);
            }
        }
#pragma unroll
        for (int e = 0; e < 8; ++e) {
            float hv = h[e];
            sH[warp][e][lane] = hv * (1.0f / (1.0f + expf(-hv)));
        }
    }
    __syncwarp();

    {
        const int e = lane >> 2;
        const int h0 = lane & 3, h1 = h0 + 4;
        float a0 = sB2[h0], a1 = sB2[h1];
#pragma unroll
        for (int c4 = 0; c4 < 32; c4 += 4) {
            float4 hv = *(const float4*)&sH[warp][e][c4];
            float4 wa = *(const float4*)&sW2T[h0][c4];
            float4 wb = *(const float4*)&sW2T[h1][c4];
            a0 = __fmaf_rn(hv.x, wa.x, a0); a1 = __fmaf_rn(hv.x, wb.x, a1);
            a0 = __fmaf_rn(hv.y, wa.y, a0); a1 = __fmaf_rn(hv.y, wb.y, a1);
            a0 = __fmaf_rn(hv.z, wa.z, a0); a1 = __fmaf_rn(hv.z, wb.z, a1);
            a0 = __fmaf_rn(hv.w, wa.w, a0); a1 = __fmaf_rn(hv.w, wb.w, a1);
        }
        g_logit[(e0+e)*HEADS + h0] = a0;
        g_logit[(e0+e)*HEADS + h1] = a1;
    }
}

// ---------------- kernel 4: softmax + aggregate + epilogues -----------------
__global__ __launch_bounds__(256) void agg_kernel(
    const float* __restrict__ X, const float* __restrict__ bbr,
    const int* __restrict__ noise,
    const float* __restrict__ wo,   const float* __restrict__ bo,
    const float* __restrict__ wg,   const float* __restrict__ bg,
    const float* __restrict__ wf,   const float* __restrict__ bf,
    const float* __restrict__ wxca,
    const float* __restrict__ wgate, const float* __restrict__ bgate,
    const float* __restrict__ wbb,
    float* __restrict__ out)
{
    __shared__ float sal[EPN*HEADS];
    __shared__ int   ssrc[EPN];
    __shared__ float spart[4][LL*HV];
    __shared__ float sagg[LL*HV];
    __shared__ float sout0[LL*BBC];
    __shared__ float soutf[LL*BBC];
    __shared__ float sgate[BBC];
    __shared__ float svec[3];
    __shared__ float sg2;
    __shared__ float subb[9];
    const int i = blockIdx.x;
    const int t = threadIdx.x;

    for (int idx = t; idx < EPN*HEADS; idx += 256) sal[idx] = g_logit[i*EPN*HEADS + idx];
    if (t < EPN) ssrc[t] = g_src[i*EPN + t];
    __syncthreads();

    if (t < 64) {
        const int h = t >> 3, sub = t & 7;
        float m = -3.4e38f;
        for (int e = sub; e < EPN; e += 8) m = fmaxf(m, sal[e*HEADS + h]);
#pragma unroll
        for (int o = 1; o < 8; o <<= 1) m = fmaxf(m, __shfl_xor_sync(0xffffffffu, m, o, 8));
        float Z = 0.f;
        for (int e = sub; e < EPN; e += 8) {
            float pp = expf(sal[e*HEADS + h] - m);
            sal[e*HEADS + h] = pp;
            Z += pp;
        }
#pragma unroll
        for (int o = 1; o < 8; o <<= 1) Z += __shfl_xor_sync(0xffffffffu, Z, o, 8);
        float inv = 1.0f / (Z + 1e-9f);
        for (int e = sub; e < EPN; e += 8) sal[e*HEADS + h] *= inv;
    }
    __syncthreads();

    // gather-aggregate from plane-major fp16 v (1 wavefront per warp-load)
    {
        const int d = t & 63, g = t >> 6;
        float acc[LL];
#pragma unroll
        for (int l = 0; l < LL; ++l) acc[l] = 0.f;
        const int h = d >> 3;
        for (int e = g; e < EPN; e += 8) {
            const int e2 = e + 4;
            const bool has2 = (e2 < EPN);
            int s0 = ssrc[e];
            int s1 = has2 ? ssrc[e2] : s0;
            float al0 = sal[e*HEADS + h];
            float al1 = has2 ? sal[e2*HEADS + h] : 0.f;
            const __half2* p0 = g_vp + (size_t)s0*VSTR + d;
            const __half2* p1 = g_vp + (size_t)s1*VSTR + d;
#pragma unroll
            for (int k = 0; k < 4; ++k) {
                float2 f0 = __half22float2(p0[k*64]);
                float2 f1 = __half22float2(p1[k*64]);
                acc[2*k]   = __fmaf_rn(al0, f0.x, __fmaf_rn(al1, f1.x, acc[2*k]));
                acc[2*k+1] = __fmaf_rn(al0, f0.y, __fmaf_rn(al1, f1.y, acc[2*k+1]));
            }
            {
                float2 f0 = __half22float2(p0[256]);
                float2 f1 = __half22float2(p1[256]);
                acc[8] = __fmaf_rn(al0, f0.x, __fmaf_rn(al1, f1.x, acc[8]));
            }
        }
#pragma unroll
        for (int l = 0; l < LL; ++l) spart[g][l*HV + d] = acc[l];
    }
    __syncthreads();
    for (int idx = t; idx < LL*HV; idx += 256)
        sagg[idx] = ((spart[0][idx] + spart[1][idx]) + spart[2][idx]) + spart[3][idx];
    __syncthreads();

    for (int idx = t; idx < LL*BBC; idx += 256) {
        int l = idx >> 5, d = idx & 31;
        const float* w = wo + c_L3[l]*HV*BBC;
        float acc = 0.f;
#pragma unroll 8
        for (int c = 0; c < HV; ++c) acc = __fmaf_rn(sagg[l*HV + c], w[c*BBC + d], acc);
        if (l == 0) acc += bo[d];
        sout0[idx] = acc;
    }
    __syncthreads();

    if (t < BBC) {
        float g = 0.f;
        for (int c = 0; c < BBC; ++c) g = __fmaf_rn(sout0[c], wg[c*BBC + t], g);
        g += bg[t];
        sgate[t] = g * (1.0f / (1.0f + expf(-g)));
    }
    __syncthreads();

    for (int idx = t; idx < LL*BBC; idx += 256) {
        int l = idx >> 5, d = idx & 31;
        const float* w = wf + c_L3[l]*BBC*BBC;
        float acc = 0.f;
#pragma unroll 8
        for (int c = 0; c < BBC; ++c) acc = __fmaf_rn(sout0[l*BBC + c], w[c*BBC + d], acc);
        if (l == 0) acc += bf[d];
        float val = sout0[idx] + acc * sgate[d];
        soutf[idx] = val;
        out[OFF_OUT + (size_t)i*LL*BBC + idx] = val;
    }
    __syncthreads();

    if (t < 3) {
        float acc = 0.f;
        for (int c = 0; c < BBC; ++c) acc = __fmaf_rn(soutf[(1+t)*BBC + c], wxca[BBC + c], acc);
        svec[t] = acc;
    }
    if (t == 3) {
        float s = 0.f;
        for (int c = 0; c < BBC; ++c) s = __fmaf_rn(soutf[c], wgate[c], s);
        s += bgate[0];
        sg2 = fmaxf(s, 0.f) + log1pf(expf(-fabsf(s)));
    }
    if (t >= 8 && t < 17) {
        int idx = t - 8;
        int k = idx / 3, m = idx - 3*k;
        float acc = 0.f;
        for (int c = 0; c < BBC; ++c) acc = __fmaf_rn(soutf[(1+k)*BBC + c], wbb[(BBC + c)*NBB + m], acc);
        subb[idx] = acc;
    }
    __syncthreads();

    const int nz = noise[i];
    if (t < 3)
        out[(size_t)i*3 + t] = X[i*3+t] + (nz ? svec[t]*sg2 : 0.f);
    if (t >= 8 && t < 17) {
        int idx = t - 8;
        int m = idx / 3, k = idx - 3*m;
        out[OFF_BB + (size_t)i*9 + idx] = bbr[(size_t)i*9 + idx] + (nz ? subb[k*3 + m] : 0.f);
    }
}

// ---------------- launch ----------------------------------------------------
extern "C" void kernel_launch(void* const* d_in, const int* in_sizes, int n_in,
                              void* d_out, int out_size)
{
    const float* X      = (const float*)d_in[0];
    const float* bbr    = (const float*)d_in[1];
    const float* bbf    = (const float*)d_in[2];
    const int*   xmask  = (const int*)d_in[4];
    const int*   noise  = (const int*)d_in[5];
    const float* w1     = (const float*)d_in[6];
    const float* b1     = (const float*)d_in[7];
    const float* w2     = (const float*)d_in[8];
    const float* b2     = (const float*)d_in[9];
    const float* wv     = (const float*)d_in[10];
    const float* bv     = (const float*)d_in[11];
    const float* wo     = (const float*)d_in[12];
    const float* bo     = (const float*)d_in[13];
    const float* wg     = (const float*)d_in[14];
    const float* bg     = (const float*)d_in[15];
    const float* wf     = (const float*)d_in[16];
    const float* bf     = (const float*)d_in[17];
    const float* wxca   = (const float*)d_in[18];
    const float* wgate  = (const float*)d_in[20];
    const float* bgate  = (const float*)d_in[21];
    const float* wbb    = (const float*)d_in[22];
    float* out = (float*)d_out;

    node_v_kernel<<<NN/NVB, 512>>>(bbf, bbr, noise, xmask, X, wv, bv, w1, b1);
    row_kernel<<<NN, 256>>>(xmask);
    edge_kernel<<<NN*EPN/EPB, 256>>>(w1, w2, b2);
    agg_kernel<<<NN, 256>>>(X, bbr, noise, wo, bo, wg, bg, wf, bf,
                            wxca, wgate, bgate, wbb, out);
}

// round 14
// speedup vs baseline: 1.5675x; 1.5675x over previous
#include <cuda_runtime.h>
#include <cuda_fp16.h>
#include <math.h>

// ---------------- problem constants ----------------
#define NN    4096
#define KNNK  20
#define LRKK  40
#define EPN   60
#define LL    9
#define SPH   35
#define BBC   32
#define NBB   3
#define HEADS 8
#define HV    64
#define HC    32
#define EPB   64
#define NVB   8
#define CAP   3072

#define OFF_BB  (NN*3)
#define OFF_OUT (NN*3 + NN*9)

__device__ int     g_src[NN*EPN];
__device__ float   g_logit[NN*EPN*HEADS];
__device__ float   g_inv[NN*SPH];
__device__ __half2 g_vh[NN*HV*5];   // [node][d][5 half2] = 9 v-values + pad (R12-proven)
__device__ float   g_hsrc[NN*HC];
__device__ float   g_hdst[NN*HC];
__device__ float4  g_xp[NN];        // [x,y,z,x2]; x2=+inf if x_mask

__constant__ int c_L3[LL] = {0,1,1,1,2,2,2,2,2};

// ---------------- threefry2x32 lr key (JAX partitionable path) --------------
__device__ __forceinline__ float lr_key(unsigned int idx, float d2e) {
    unsigned int x0 = 0u, x1 = idx;
    const unsigned int ks0 = 0u, ks1 = 1u, ks2 = 0x1BD11BDBu;
    x0 += ks0; x1 += ks1;
#define TFR(r) { x0 += x1; x1 = __funnelshift_l(x1, x1, (r)); x1 ^= x0; }
    TFR(13) TFR(15) TFR(26) TFR(6);  x0 += ks1; x1 += ks2 + 1u;
    TFR(17) TFR(29) TFR(16) TFR(24); x0 += ks2; x1 += ks0 + 2u;
    TFR(13) TFR(15) TFR(26) TFR(6);  x0 += ks0; x1 += ks1 + 3u;
    TFR(17) TFR(29) TFR(16) TFR(24); x0 += ks1; x1 += ks2 + 4u;
    TFR(13) TFR(15) TFR(26) TFR(6);  x0 += ks2; x1 += ks0 + 5u;
#undef TFR
    unsigned int bits = x0 ^ x1;
    float u = __uint_as_float((bits >> 9) | 0x3f800000u) - 1.0f;
    u = fmaxf(u, 1.17549435e-38f);
    float w = -__logf(u);
    return w * (d2e * __fsqrt_rn(d2e));
}

// ---------------- kernel 1: node features + V(fp16) + partials + xp ---------
__global__ __launch_bounds__(512) void node_v_kernel(
    const float* __restrict__ bbf, const float* __restrict__ bbr,
    const int* __restrict__ noise, const int* __restrict__ xmask,
    const float* __restrict__ X,
    const float* __restrict__ wv, const float* __restrict__ bv,
    const float* __restrict__ w1, const float* __restrict__ b1)
{
    __shared__ float sWV[3*SPH*HV];
    __shared__ float sW1[2*SPH*HC];
    __shared__ float nf[NVB][LL*SPH];
    const int t = threadIdx.x;
    for (int idx = t; idx < 3*SPH*HV; idx += 512) sWV[idx] = wv[idx];
    for (int idx = t; idx < 2*SPH*HC; idx += 512) sW1[idx] = w1[idx];

    const int g = t >> 6;
    const int tt = t & 63;
    const int i = blockIdx.x*NVB + g;

    for (int idx = tt; idx < LL*SPH; idx += 64) {
        int l = idx / SPH, c = idx - l*SPH;
        float v = 0.f;
        if (c < BBC)                    v = bbf[(i*LL + l)*BBC + c];
        else if (l >= 1 && l <= 3)      v = bbr[(i*NBB + (c-BBC))*3 + (l-1)];
        if (l == 0 && c == SPH-1)       v = noise[i] ? 1.0f : 0.0f;
        nf[g][idx] = v;
    }
    if (tt == 0) {
        float x = X[3*i], y = X[3*i+1], z = X[3*i+2];
        float x2 = __fadd_rn(__fadd_rn(__fmul_rn(x,x),__fmul_rn(y,y)),__fmul_rn(z,z));
        g_xp[i] = make_float4(x, y, z, xmask[i] ? __int_as_float(0x7F800000) : x2);
    }
    __syncthreads();
    if (tt < SPH) g_inv[i*SPH + tt] = nf[g][tt];

    if (tt < HC) {
        float acc = b1[tt];
#pragma unroll 7
        for (int c = 0; c < SPH; ++c) acc = __fmaf_rn(nf[g][c], sW1[c*HC + tt], acc);
        g_hsrc[i*HC + tt] = acc;
    } else {
        int d = tt - HC;
        float acc = 0.f;
#pragma unroll 7
        for (int c = 0; c < SPH; ++c) acc = __fmaf_rn(nf[g][c], sW1[(SPH + c)*HC + d], acc);
        g_hdst[i*HC + d] = acc;
    }

    {
        const int d = tt;
        float va[LL];
#pragma unroll
        for (int l = 0; l < LL; ++l) {
            const float* w = sWV + c_L3[l]*SPH*HV;
            float acc = 0.f;
#pragma unroll 7
            for (int c = 0; c < SPH; ++c) acc = __fmaf_rn(nf[g][l*SPH + c], w[c*HV + d], acc);
            if (l == 0) acc += bv[d];
            va[l] = acc;
        }
        __half2* dst = g_vh + ((size_t)i*HV + d)*5;
        dst[0] = __floats2half2_rn(va[0], va[1]);
        dst[1] = __floats2half2_rn(va[2], va[3]);
        dst[2] = __floats2half2_rn(va[4], va[5]);
        dst[3] = __floats2half2_rn(va[6], va[7]);
        dst[4] = __floats2half2_rn(va[8], 0.f);
    }
}

// ---------------- radix-select with candidate compaction --------------------
#define PICK(BYTE)                                                             \
    {                                                                          \
        unsigned cnt = 0;                                                      \
        _Pragma("unroll")                                                      \
        for (int c = 0; c < 8; ++c) cnt += hist[c][t];                         \
        unsigned v = cnt;                                                      \
        _Pragma("unroll")                                                      \
        for (int o = 1; o < 32; o <<= 1) {                                     \
            unsigned n = __shfl_up_sync(0xffffffffu, v, o);                    \
            if (lane >= o) v += n;                                             \
        }                                                                      \
        if (lane == 31) sScan[w] = v;                                          \
        __syncthreads();                                                       \
        if (t == 0) {                                                          \
            unsigned a = 0;                                                    \
            _Pragma("unroll")                                                  \
            for (int c = 0; c < 8; ++c) { unsigned x = sScan[c]; sScan[c] = a; a += x; } \
        }                                                                      \
        __syncthreads();                                                       \
        unsigned incl = v + sScan[w];                                          \
        unsigned excl = incl - cnt;                                            \
        if (kk > excl && kk <= incl) { sScan[8] = (unsigned)t; sScan[9] = excl; } \
        __syncthreads();                                                       \
        prefix |= sScan[8] << (8*(BYTE));                                      \
        kk -= sScan[9];                                                        \
        __syncthreads();                                                       \
    }

// Find k-th smallest among keys < validMax. Byte-3 histogram must be pre-built.
// Side effects: sCnt[0] = candidate count (byte-3 bin members);
//               sCnt[3] = count of keys in byte-3 bins BELOW the selected bin.
__device__ __forceinline__ uint2 radix_select(
    const unsigned* s_key, unsigned (*hist)[256], unsigned* sScan,
    unsigned short* cand, unsigned* sCnt,
    unsigned k, unsigned validMax, int t)
{
    const int lane = t & 31, w = t >> 5;
    unsigned prefix = 0, kk = k;

    PICK(3)
    if (t == 0) sCnt[3] = sScan[9];   // keys strictly below selected byte-3 bin

    if (t == 0) sCnt[0] = 0;
    __syncthreads();
    const unsigned b3 = prefix >> 24;
    for (int j = t; j < NN; j += 256) {
        unsigned u = s_key[j];
        if (u < validMax && (u >> 24) == b3) {
            unsigned p = atomicAdd(&sCnt[0], 1u);
            if (p < CAP) cand[p] = (unsigned short)j;
        }
    }
    __syncthreads();
    const int candN = (int)sCnt[0];
    const bool useCand = (candN <= CAP);

#pragma unroll
    for (int byte = 2; byte >= 0; --byte) {
        const unsigned maskHi = 0xFFFFFFFFu << (8*(byte+1));
#pragma unroll
        for (int c = 0; c < 8; ++c) hist[c][t] = 0;
        __syncthreads();
        if (useCand) {
            for (int c = t; c < candN; c += 256) {
                unsigned u = s_key[cand[c]];
                if ((u & maskHi) == prefix)
                    atomicAdd(&hist[w][(u >> (8*byte)) & 255u], 1u);
            }
        } else {
            for (int j = t; j < NN; j += 256) {
                unsigned u = s_key[j];
                if (u < validMax && (u & maskHi) == prefix)
                    atomicAdd(&hist[w][(u >> (8*byte)) & 255u], 1u);
            }
        }
        __syncthreads();
        PICK(byte)
    }
    return make_uint2(prefix, kk);
}

// ---------------- kernel 2: distances + knn top20 + lr top40 ---------------
__global__ __launch_bounds__(256) void row_kernel(
    const int* __restrict__ xmask)
{
    __shared__ unsigned s_key[NN];
    __shared__ unsigned s_hist[8][256];
    __shared__ unsigned sScan[10];
    __shared__ unsigned short sCand[CAP];
    __shared__ unsigned sCnt[4];
    __shared__ int      sSel[EPN];
    __shared__ int      sTie[64];
    const int i = blockIdx.x;
    const int t = threadIdx.x;
    const int w = t >> 5;
    const unsigned U_INV = __float_as_uint(1e30f);

    if (xmask[i] != 0) {
        for (int e = t; e < EPN; e += 256)
            g_src[i*EPN + e] = (e < KNNK) ? e : (e - KNNK);
        return;
    }

    const float4 pi = g_xp[i];
    const float xi = pi.x, yi = pi.y, zi = pi.z, x2i = pi.w;
    const int bi = i >> 11;

#pragma unroll
    for (int c = 0; c < 8; ++c) s_hist[c][t] = 0;
    __syncthreads();
    for (int j = t; j < NN; j += 256) {
        float4 p = g_xp[j];
        float dot = __fmul_rn(xi, p.x);
        dot = __fmaf_rn(yi, p.y, dot);
        dot = __fmaf_rn(zi, p.z, dot);
        float d2  = fmaxf(__fsub_rn(__fadd_rn(x2i, p.w), __fmul_rn(2.0f, dot)), 0.0f);
        bool invalid = ((j >> 11) != bi) || (j == i);
        unsigned u = invalid ? U_INV : __float_as_uint(d2);
        s_key[j] = u;
        if (u < U_INV) atomicAdd(&s_hist[w][u >> 24], 1u);
    }
    __syncthreads();

    // ================= knn stage =================
    {
        uint2 rk = radix_select(s_key, s_hist, sScan, sCand, sCnt, KNNK, U_INV, t);
        const unsigned T = rk.x;
        const int need = (int)rk.y;
        const int cLess = KNNK - need;
        const int candN = (int)sCnt[0];
        const bool fromCand = (sCnt[3] == 0u) && (candN <= CAP);

        if (t == 0) { sCnt[1] = 0; sCnt[2] = 0; }
        __syncthreads();
        if (fromCand) {
            for (int c = t; c < candN; c += 256) {
                int j = (int)sCand[c];
                unsigned u = s_key[j];
                if (u < T) {
                    int p = (int)atomicAdd(&sCnt[1], 1u);
                    sSel[p] = j;
                } else if (u == T) {
                    int p = (int)atomicAdd(&sCnt[2], 1u);
                    if (p < 64) sTie[p] = j;
                }
            }
        } else {
            for (int j = t; j < NN; j += 256) {
                unsigned u = s_key[j];
                if (u < T) {
                    int p = (int)atomicAdd(&sCnt[1], 1u);
                    sSel[p] = j;
                } else if (u == T) {
                    int p = (int)atomicAdd(&sCnt[2], 1u);
                    if (p < 64) sTie[p] = j;
                }
            }
        }
        __syncthreads();
        if (t == 0) {   // lowest-index ties (JAX stable top_k)
            int nt = min((int)sCnt[2], 64);
            int last = -1;
            for (int r = 0; r < need; ++r) {
                int best = 0x7FFFFFFF;
                for (int q = 0; q < nt; ++q) { int j = sTie[q]; if (j > last && j < best) best = j; }
                sSel[cLess + r] = best;
                last = best;
            }
        }
        __syncthreads();
        if (t < KNNK) {   // deterministic ascending-index order + mark selected
            int myj = sSel[t];
            int rank = 0;
#pragma unroll 4
            for (int q = 0; q < KNNK; ++q) rank += (sSel[q] < myj);
            g_src[i*EPN + rank] = myj;
            s_key[myj] = U_INV;
        }
        __syncthreads();
    }

#pragma unroll
    for (int c = 0; c < 8; ++c) s_hist[c][t] = 0;
    __syncthreads();
    for (int j = t; j < NN; j += 256) {
        unsigned u = s_key[j];
        unsigned outk = U_INV;
        if (u < U_INV) {
            float d2e = __fadd_rn(__uint_as_float(u), 1e-6f);
            float s = lr_key((unsigned)(i*NN + j), d2e);
            outk = __float_as_uint(s);
            atomicAdd(&s_hist[w][outk >> 24], 1u);
        }
        s_key[j] = outk;
    }
    __syncthreads();

    // ================= lr stage =================
    {
        uint2 rk = radix_select(s_key, s_hist, sScan, sCand, sCnt, LRKK, U_INV, t);
        const unsigned T = rk.x;
        const int need = (int)rk.y;
        const int cLess = LRKK - need;
        const int candN = (int)sCnt[0];
        const bool fromCand = (sCnt[3] == 0u) && (candN <= CAP);

        if (t == 0) { sCnt[1] = 0; sCnt[2] = 0; }
        __syncthreads();
        if (fromCand) {
            for (int c = t; c < candN; c += 256) {
                int j = (int)sCand[c];
                unsigned u = s_key[j];
                if (u < T) {
                    int p = (int)atomicAdd(&sCnt[1], 1u);
                    sSel[p] = j;
                } else if (u == T) {
                    int p = (int)atomicAdd(&sCnt[2], 1u);
                    if (p < 64) sTie[p] = j;
                }
            }
        } else {
            for (int j = t; j < NN; j += 256) {
                unsigned u = s_key[j];
                if (u < T) {
                    int p = (int)atomicAdd(&sCnt[1], 1u);
                    sSel[p] = j;
                } else if (u == T) {
                    int p = (int)atomicAdd(&sCnt[2], 1u);
                    if (p < 64) sTie[p] = j;
                }
            }
        }
        __syncthreads();
        if (t == 0) {
            int nt = min((int)sCnt[2], 64);
            int last = -1;
            for (int r = 0; r < need; ++r) {
                int best = 0x7FFFFFFF;
                for (int q = 0; q < nt; ++q) { int j = sTie[q]; if (j > last && j < best) best = j; }
                sSel[cLess + r] = best;
                last = best;
            }
        }
        __syncthreads();
        if (t < LRKK) {
            int myj = sSel[t];
            int rank = 0;
#pragma unroll 4
            for (int q = 0; q < LRKK; ++q) rank += (sSel[q] < myj);
            g_src[i*EPN + KNNK + rank] = myj;
        }
    }
}

// ---------------- kernel 3: edge MLP (factorized; 8 edges per warp) ---------
__global__ __launch_bounds__(256) void edge_kernel(
    const float* __restrict__ w1,
    const float* __restrict__ w2, const float* __restrict__ b2)
{
    __shared__ float sW1eT[HC][36];
    __shared__ float sW2T[HEADS][36];
    __shared__ float sB2[HEADS];
    __shared__ float sEF[8][8][40];
    __shared__ float sH[8][8][40];
    const int t = threadIdx.x, lane = t & 31, warp = t >> 5;
    for (int idx = t; idx < HC*32; idx += 256) {
        int h = idx >> 5, c = idx & 31;
        sW1eT[h][c] = w1[(2*SPH + c)*HC + h];
    }
    for (int idx = t; idx < HEADS*32; idx += 256) {
        int h = idx >> 5, c = idx & 31;
        sW2T[h][c] = w2[c*HEADS + h];
    }
    if (t < HEADS) sB2[t] = b2[t];
    __syncthreads();

    const int e0 = blockIdx.x*EPB + warp*8;

    {
        const int e = lane >> 2, q = lane & 3;
        const int edge = e0 + e;
        const int ii = edge / EPN;
        const int ss = g_src[edge];
        float4 ps = g_xp[ss], pd = g_xp[ii];
        float dx = ps.x-pd.x, dy = ps.y-pd.y, dz = ps.z-pd.z;
        float dist = sqrtf(__fadd_rn(__fadd_rn(__fmul_rn(dx,dx),__fmul_rn(dy,dy)),__fmul_rn(dz,dz)));
        if (q < 2) {
#pragma unroll
            for (int r = 0; r < 8; ++r) {
                int f = q*8 + r;
                float mu = (float)f * (20.0f/15.0f);
                float zz = (dist - mu) * 0.8f;
                sEF[warp][e][f] = expf(-zz*zz);
            }
        } else {
            float dfl = (float)(ss - ii);
#pragma unroll
            for (int r = 0; r < 4; ++r) {
                int k = (q-2)*4 + r;
                float fr = expf((float)(2*k) * -0.5756462732485114f);
                float sv, cv;
                sincosf(dfl * fr, &sv, &cv);
                sEF[warp][e][16 + k] = cv;
                sEF[warp][e][24 + k] = sv;
            }
        }
    }
    __syncwarp();

    {
        float h[8];
#pragma unroll
        for (int e = 0; e < 8; ++e) {
            const int edge = e0 + e;
            const int ii = edge / EPN;
            const int ss = g_src[edge];
            h[e] = g_hsrc[ss*HC + lane] + g_hdst[ii*HC + lane];
        }
#pragma unroll
        for (int c4 = 0; c4 < 32; c4 += 4) {
            float4 w4 = *(const float4*)&sW1eT[lane][c4];
#pragma unroll
            for (int e = 0; e < 8; ++e) {
                float4 f4 = *(const float4*)&sEF[warp][e][c4];
                h[e] = __fmaf_rn(f4.x, w4.x, h[e]);
                h[e] = __fmaf_rn(f4.y, w4.y, h[e]);
                h[e] = __fmaf_rn(f4.z, w4.z, h[e]);
                h[e] = __fmaf_rn(f4.w, w4.w, h[e]);
            }
        }
#pragma unroll
        for (int e = 0; e < 8; ++e) {
            float hv = h[e];
            sH[warp][e][lane] = hv * (1.0f / (1.0f + expf(-hv)));
        }
    }
    __syncwarp();

    {
        const int e = lane >> 2;
        const int h0 = lane & 3, h1 = h0 + 4;
        float a0 = sB2[h0], a1 = sB2[h1];
#pragma unroll
        for (int c4 = 0; c4 < 32; c4 += 4) {
            float4 hv = *(const float4*)&sH[warp][e][c4];
            float4 wa = *(const float4*)&sW2T[h0][c4];
            float4 wb = *(const float4*)&sW2T[h1][c4];
            a0 = __fmaf_rn(hv.x, wa.x, a0); a1 = __fmaf_rn(hv.x, wb.x, a1);
            a0 = __fmaf_rn(hv.y, wa.y, a0); a1 = __fmaf_rn(hv.y, wb.y, a1);
            a0 = __fmaf_rn(hv.z, wa.z, a0); a1 = __fmaf_rn(hv.z, wb.z, a1);
            a0 = __fmaf_rn(hv.w, wa.w, a0); a1 = __fmaf_rn(hv.w, wb.w, a1);
        }
        g_logit[(e0+e)*HEADS + h0] = a0;
        g_logit[(e0+e)*HEADS + h1] = a1;
    }
}

// ---------------- kernel 4: softmax + aggregate + epilogues -----------------
__global__ __launch_bounds__(256) void agg_kernel(
    const float* __restrict__ X, const float* __restrict__ bbr,
    const int* __restrict__ noise,
    const float* __restrict__ wo,   const float* __restrict__ bo,
    const float* __restrict__ wg,   const float* __restrict__ bg,
    const float* __restrict__ wf,   const float* __restrict__ bf,
    const float* __restrict__ wxca,
    const float* __restrict__ wgate, const float* __restrict__ bgate,
    const float* __restrict__ wbb,
    float* __restrict__ out)
{
    __shared__ float sal[EPN*HEADS];
    __shared__ int   ssrc[EPN];
    __shared__ float spart[4][LL*HV];
    __shared__ float sagg[LL*HV];
    __shared__ float sout0[LL*BBC];
    __shared__ float soutf[LL*BBC];
    __shared__ float sgate[BBC];
    __shared__ float svec[3];
    __shared__ float sg2;
    __shared__ float subb[9];
    const int i = blockIdx.x;
    const int t = threadIdx.x;

    for (int idx = t; idx < EPN*HEADS; idx += 256) sal[idx] = g_logit[i*EPN*HEADS + idx];
    if (t < EPN) ssrc[t] = g_src[i*EPN + t];
    __syncthreads();

    if (t < 64) {
        const int h = t >> 3, sub = t & 7;
        float m = -3.4e38f;
        for (int e = sub; e < EPN; e += 8) m = fmaxf(m, sal[e*HEADS + h]);
#pragma unroll
        for (int o = 1; o < 8; o <<= 1) m = fmaxf(m, __shfl_xor_sync(0xffffffffu, m, o, 8));
        float Z = 0.f;
        for (int e = sub; e < EPN; e += 8) {
            float pp = expf(sal[e*HEADS + h] - m);
            sal[e*HEADS + h] = pp;
            Z += pp;
        }
#pragma unroll
        for (int o = 1; o < 8; o <<= 1) Z += __shfl_xor_sync(0xffffffffu, Z, o, 8);
        float inv = 1.0f / (Z + 1e-9f);
        for (int e = sub; e < EPN; e += 8) sal[e*HEADS + h] *= inv;
    }
    __syncthreads();

    // gather-aggregate from fp16 v (R12-proven form: 5x half2, 2-edge unroll)
    {
        const int d = t & 63, g = t >> 6;
        float acc[LL];
#pragma unroll
        for (int l = 0; l < LL; ++l) acc[l] = 0.f;
        const int h = d >> 3;
        for (int e = g; e < EPN; e += 8) {
            const int e2 = e + 4;
            const bool has2 = (e2 < EPN);
            int s0 = ssrc[e];
            int s1 = has2 ? ssrc[e2] : s0;
            float al0 = sal[e*HEADS + h];
            float al1 = has2 ? sal[e2*HEADS + h] : 0.f;
            const __half2* p0 = g_vh + ((size_t)s0*HV + d)*5;
            const __half2* p1 = g_vh + ((size_t)s1*HV + d)*5;
#pragma unroll
            for (int k = 0; k < 4; ++k) {
                float2 f0 = __half22float2(p0[k]);
                float2 f1 = __half22float2(p1[k]);
                acc[2*k]   = __fmaf_rn(al0, f0.x, __fmaf_rn(al1, f1.x, acc[2*k]));
                acc[2*k+1] = __fmaf_rn(al0, f0.y, __fmaf_rn(al1, f1.y, acc[2*k+1]));
            }
            {
                float2 f0 = __half22float2(p0[4]);
                float2 f1 = __half22float2(p1[4]);
                acc[8] = __fmaf_rn(al0, f0.x, __fmaf_rn(al1, f1.x, acc[8]));
            }
        }
#pragma unroll
        for (int l = 0; l < LL; ++l) spart[g][l*HV + d] = acc[l];
    }
    __syncthreads();
    for (int idx = t; idx < LL*HV; idx += 256)
        sagg[idx] = ((spart[0][idx] + spart[1][idx]) + spart[2][idx]) + spart[3][idx];
    __syncthreads();

    for (int idx = t; idx < LL*BBC; idx += 256) {
        int l = idx >> 5, d = idx & 31;
        const float* w = wo + c_L3[l]*HV*BBC;
        float acc = 0.f;
#pragma unroll 8
        for (int c = 0; c < HV; ++c) acc = __fmaf_rn(sagg[l*HV + c], w[c*BBC + d], acc);
        if (l == 0) acc += bo[d];
        sout0[idx] = acc;
    }
    __syncthreads();

    if (t < BBC) {
        float g = 0.f;
        for (int c = 0; c < BBC; ++c) g = __fmaf_rn(sout0[c], wg[c*BBC + t], g);
        g += bg[t];
        sgate[t] = g * (1.0f / (1.0f + expf(-g)));
    }
    __syncthreads();

    for (int idx = t; idx < LL*BBC; idx += 256) {
        int l = idx >> 5, d = idx & 31;
        const float* w = wf + c_L3[l]*BBC*BBC;
        float acc = 0.f;
#pragma unroll 8
        for (int c = 0; c < BBC; ++c) acc = __fmaf_rn(sout0[l*BBC + c], w[c*BBC + d], acc);
        if (l == 0) acc += bf[d];
        float val = sout0[idx] + acc * sgate[d];
        soutf[idx] = val;
        out[OFF_OUT + (size_t)i*LL*BBC + idx] = val;
    }
    __syncthreads();

    if (t < 3) {
        float acc = 0.f;
        for (int c = 0; c < BBC; ++c) acc = __fmaf_rn(soutf[(1+t)*BBC + c], wxca[BBC + c], acc);
        svec[t] = acc;
    }
    if (t == 3) {
        float s = 0.f;
        for (int c = 0; c < BBC; ++c) s = __fmaf_rn(soutf[c], wgate[c], s);
        s += bgate[0];
        sg2 = fmaxf(s, 0.f) + log1pf(expf(-fabsf(s)));
    }
    if (t >= 8 && t < 17) {
        int idx = t - 8;
        int k = idx / 3, m = idx - 3*k;
        float acc = 0.f;
        for (int c = 0; c < BBC; ++c) acc = __fmaf_rn(soutf[(1+k)*BBC + c], wbb[(BBC + c)*NBB + m], acc);
        subb[idx] = acc;
    }
    __syncthreads();

    const int nz = noise[i];
    if (t < 3)
        out[(size_t)i*3 + t] = X[i*3+t] + (nz ? svec[t]*sg2 : 0.f);
    if (t >= 8 && t < 17) {
        int idx = t - 8;
        int m = idx / 3, k = idx - 3*m;
        out[OFF_BB + (size_t)i*9 + idx] = bbr[(size_t)i*9 + idx] + (nz ? subb[k*3 + m] : 0.f);
    }
}

// ---------------- launch ----------------------------------------------------
extern "C" void kernel_launch(void* const* d_in, const int* in_sizes, int n_in,
                              void* d_out, int out_size)
{
    const float* X      = (const float*)d_in[0];
    const float* bbr    = (const float*)d_in[1];
    const float* bbf    = (const float*)d_in[2];
    const int*   xmask  = (const int*)d_in[4];
    const int*   noise  = (const int*)d_in[5];
    const float* w1     = (const float*)d_in[6];
    const float* b1     = (const float*)d_in[7];
    const float* w2     = (const float*)d_in[8];
    const float* b2     = (const float*)d_in[9];
    const float* wv     = (const float*)d_in[10];
    const float* bv     = (const float*)d_in[11];
    const float* wo     = (const float*)d_in[12];
    const float* bo     = (const float*)d_in[13];
    const float* wg     = (const float*)d_in[14];
    const float* bg     = (const float*)d_in[15];
    const float* wf     = (const float*)d_in[16];
    const float* bf     = (const float*)d_in[17];
    const float* wxca   = (const float*)d_in[18];
    const float* wgate  = (const float*)d_in[20];
    const float* bgate  = (const float*)d_in[21];
    const float* wbb    = (const float*)d_in[22];
    float* out = (float*)d_out;

    node_v_kernel<<<NN/NVB, 512>>>(bbf, bbr, noise, xmask, X, wv, bv, w1, b1);
    row_kernel<<<NN, 256>>>(xmask);
    edge_kernel<<<NN*EPN/EPB, 256>>>(w1, w2, b2);
    agg_kernel<<<NN, 256>>>(X, bbr, noise, wo, bo, wg, bg, wf, bf,
                            wxca, wgate, bgate, wbb, out);
}

// round 15
// speedup vs baseline: 1.7581x; 1.1216x over previous
#include <cuda_runtime.h>
#include <cuda_fp16.h>
#include <math.h>

// ---------------- problem constants ----------------
#define NN    4096
#define NL    2048         // nodes per chain (batch = repeat(arange(2), 2048))
#define KNNK  20
#define LRKK  40
#define EPN   60
#define LL    9
#define SPH   35
#define BBC   32
#define NBB   3
#define HEADS 8
#define HV    64
#define HC    32
#define EPB   64
#define NVB   8
#define CAP   2048

#define OFF_BB  (NN*3)
#define OFF_OUT (NN*3 + NN*9)

__device__ int     g_src[NN*EPN];
__device__ float   g_logit[NN*EPN*HEADS];
__device__ float   g_inv[NN*SPH];
__device__ __half2 g_vh[NN*HV*5];   // [node][d][5 half2] (R12-proven layout)
__device__ float   g_hsrc[NN*HC];
__device__ float   g_hdst[NN*HC];
__device__ float4  g_xp[NN];        // [x,y,z,x2]; x2=+inf if x_mask

__constant__ int c_L3[LL] = {0,1,1,1,2,2,2,2,2};

// ---------------- threefry2x32 lr key (JAX partitionable path) --------------
__device__ __forceinline__ float lr_key(unsigned int idx, float d2e) {
    unsigned int x0 = 0u, x1 = idx;
    const unsigned int ks0 = 0u, ks1 = 1u, ks2 = 0x1BD11BDBu;
    x0 += ks0; x1 += ks1;
#define TFR(r) { x0 += x1; x1 = __funnelshift_l(x1, x1, (r)); x1 ^= x0; }
    TFR(13) TFR(15) TFR(26) TFR(6);  x0 += ks1; x1 += ks2 + 1u;
    TFR(17) TFR(29) TFR(16) TFR(24); x0 += ks2; x1 += ks0 + 2u;
    TFR(13) TFR(15) TFR(26) TFR(6);  x0 += ks0; x1 += ks1 + 3u;
    TFR(17) TFR(29) TFR(16) TFR(24); x0 += ks1; x1 += ks2 + 4u;
    TFR(13) TFR(15) TFR(26) TFR(6);  x0 += ks2; x1 += ks0 + 5u;
#undef TFR
    unsigned int bits = x0 ^ x1;
    float u = __uint_as_float((bits >> 9) | 0x3f800000u) - 1.0f;
    u = fmaxf(u, 1.17549435e-38f);
    float w = -__logf(u);
    return w * (d2e * __fsqrt_rn(d2e));
}

// ---------------- kernel 1: node features + V(fp16) + partials + xp ---------
__global__ __launch_bounds__(512) void node_v_kernel(
    const float* __restrict__ bbf, const float* __restrict__ bbr,
    const int* __restrict__ noise, const int* __restrict__ xmask,
    const float* __restrict__ X,
    const float* __restrict__ wv, const float* __restrict__ bv,
    const float* __restrict__ w1, const float* __restrict__ b1)
{
    __shared__ float sWV[3*SPH*HV];
    __shared__ float sW1[2*SPH*HC];
    __shared__ float nf[NVB][LL*SPH];
    const int t = threadIdx.x;
    for (int idx = t; idx < 3*SPH*HV; idx += 512) sWV[idx] = wv[idx];
    for (int idx = t; idx < 2*SPH*HC; idx += 512) sW1[idx] = w1[idx];

    const int g = t >> 6;
    const int tt = t & 63;
    const int i = blockIdx.x*NVB + g;

    for (int idx = tt; idx < LL*SPH; idx += 64) {
        int l = idx / SPH, c = idx - l*SPH;
        float v = 0.f;
        if (c < BBC)                    v = bbf[(i*LL + l)*BBC + c];
        else if (l >= 1 && l <= 3)      v = bbr[(i*NBB + (c-BBC))*3 + (l-1)];
        if (l == 0 && c == SPH-1)       v = noise[i] ? 1.0f : 0.0f;
        nf[g][idx] = v;
    }
    if (tt == 0) {
        float x = X[3*i], y = X[3*i+1], z = X[3*i+2];
        float x2 = __fadd_rn(__fadd_rn(__fmul_rn(x,x),__fmul_rn(y,y)),__fmul_rn(z,z));
        g_xp[i] = make_float4(x, y, z, xmask[i] ? __int_as_float(0x7F800000) : x2);
    }
    __syncthreads();
    if (tt < SPH) g_inv[i*SPH + tt] = nf[g][tt];

    if (tt < HC) {
        float acc = b1[tt];
#pragma unroll 7
        for (int c = 0; c < SPH; ++c) acc = __fmaf_rn(nf[g][c], sW1[c*HC + tt], acc);
        g_hsrc[i*HC + tt] = acc;
    } else {
        int d = tt - HC;
        float acc = 0.f;
#pragma unroll 7
        for (int c = 0; c < SPH; ++c) acc = __fmaf_rn(nf[g][c], sW1[(SPH + c)*HC + d], acc);
        g_hdst[i*HC + d] = acc;
    }

    {
        const int d = tt;
        float va[LL];
#pragma unroll
        for (int l = 0; l < LL; ++l) {
            const float* w = sWV + c_L3[l]*SPH*HV;
            float acc = 0.f;
#pragma unroll 7
            for (int c = 0; c < SPH; ++c) acc = __fmaf_rn(nf[g][l*SPH + c], w[c*HV + d], acc);
            if (l == 0) acc += bv[d];
            va[l] = acc;
        }
        __half2* dst = g_vh + ((size_t)i*HV + d)*5;
        dst[0] = __floats2half2_rn(va[0], va[1]);
        dst[1] = __floats2half2_rn(va[2], va[3]);
        dst[2] = __floats2half2_rn(va[4], va[5]);
        dst[3] = __floats2half2_rn(va[6], va[7]);
        dst[4] = __floats2half2_rn(va[8], 0.f);
    }
}

// ---------------- radix-select (2048-domain) --------------------------------
#define PICK(BYTE)                                                             \
    {                                                                          \
        unsigned cnt = 0;                                                      \
        _Pragma("unroll")                                                      \
        for (int c = 0; c < 8; ++c) cnt += hist[c][t];                         \
        unsigned v = cnt;                                                      \
        _Pragma("unroll")                                                      \
        for (int o = 1; o < 32; o <<= 1) {                                     \
            unsigned n = __shfl_up_sync(0xffffffffu, v, o);                    \
            if (lane >= o) v += n;                                             \
        }                                                                      \
        if (lane == 31) sScan[w] = v;                                          \
        __syncthreads();                                                       \
        if (t == 0) {                                                          \
            unsigned a = 0;                                                    \
            _Pragma("unroll")                                                  \
            for (int c = 0; c < 8; ++c) { unsigned x = sScan[c]; sScan[c] = a; a += x; } \
        }                                                                      \
        __syncthreads();                                                       \
        unsigned incl = v + sScan[w];                                          \
        unsigned excl = incl - cnt;                                            \
        if (kk > excl && kk <= incl) { sScan[8] = (unsigned)t; sScan[9] = excl; } \
        __syncthreads();                                                       \
        prefix |= sScan[8] << (8*(BYTE));                                      \
        kk -= sScan[9];                                                        \
        __syncthreads();                                                       \
    }

// k-th smallest among keys < validMax over NL local indices.
__device__ __forceinline__ uint2 radix_select(
    const unsigned* s_key, unsigned (*hist)[256], unsigned* sScan,
    unsigned short* cand, unsigned* sCnt,
    unsigned k, unsigned validMax, int t)
{
    const int lane = t & 31, w = t >> 5;
    unsigned prefix = 0, kk = k;

    PICK(3)

    if (t == 0) sCnt[0] = 0;
    __syncthreads();
    const unsigned b3 = prefix >> 24;
    for (int j = t; j < NL; j += 256) {
        unsigned u = s_key[j];
        if (u < validMax && (u >> 24) == b3) {
            unsigned p = atomicAdd(&sCnt[0], 1u);
            cand[p] = (unsigned short)j;
        }
    }
    __syncthreads();
    const int candN = (int)sCnt[0];

#pragma unroll
    for (int byte = 2; byte >= 0; --byte) {
        const unsigned maskHi = 0xFFFFFFFFu << (8*(byte+1));
#pragma unroll
        for (int c = 0; c < 8; ++c) hist[c][t] = 0;
        __syncthreads();
        for (int c = t; c < candN; c += 256) {
            unsigned u = s_key[cand[c]];
            if ((u & maskHi) == prefix)
                atomicAdd(&hist[w][(u >> (8*byte)) & 255u], 1u);
        }
        __syncthreads();
        PICK(byte)
    }
    return make_uint2(prefix, kk);
}

// ---------------- kernel 2: distances + knn top20 + lr top40 ---------------
__global__ __launch_bounds__(256) void row_kernel(
    const int* __restrict__ xmask)
{
    __shared__ unsigned s_key[NL];           // 8 KB (same-chain domain only)
    __shared__ unsigned s_hist[8][256];      // 8 KB
    __shared__ unsigned sScan[10];
    __shared__ unsigned short sCand[CAP];    // 4 KB
    __shared__ unsigned sCnt[4];
    __shared__ int      sSel[EPN];
    __shared__ int      sTie[64];
    const int i = blockIdx.x;
    const int t = threadIdx.x;
    const int w = t >> 5;
    const unsigned U_INV = __float_as_uint(1e30f);

    if (xmask[i] != 0) {
        for (int e = t; e < EPN; e += 256)
            g_src[i*EPN + e] = (e < KNNK) ? e : (e - KNNK);
        return;
    }

    const float4 pi = g_xp[i];
    const float xi = pi.x, yi = pi.y, zi = pi.z, x2i = pi.w;
    const int base = (i >> 11) << 11;        // chain start
    const int iloc = i - base;

    // ---- fill keys over same-chain domain + fused byte-3 histogram
#pragma unroll
    for (int c = 0; c < 8; ++c) s_hist[c][t] = 0;
    __syncthreads();
    for (int jl = t; jl < NL; jl += 256) {
        float4 p = g_xp[base + jl];
        float dot = __fmul_rn(xi, p.x);
        dot = __fmaf_rn(yi, p.y, dot);
        dot = __fmaf_rn(zi, p.z, dot);
        float d2  = fmaxf(__fsub_rn(__fadd_rn(x2i, p.w), __fmul_rn(2.0f, dot)), 0.0f);
        unsigned u = (jl == iloc) ? U_INV : __float_as_uint(d2);  // masked j: d2=inf
        s_key[jl] = u;
        if (u < U_INV) atomicAdd(&s_hist[w][u >> 24], 1u);
    }
    __syncthreads();

    // ================= knn stage =================
    {
        uint2 rk = radix_select(s_key, s_hist, sScan, sCand, sCnt, KNNK, U_INV, t);
        const unsigned T = rk.x;
        const int need = (int)rk.y;
        const int cLess = KNNK - need;

        if (t == 0) { sCnt[1] = 0; sCnt[2] = 0; }
        __syncthreads();
        for (int jl = t; jl < NL; jl += 256) {
            unsigned u = s_key[jl];
            if (u < T) {
                int p = (int)atomicAdd(&sCnt[1], 1u);
                sSel[p] = jl;
            } else if (u == T) {
                int p = (int)atomicAdd(&sCnt[2], 1u);
                if (p < 64) sTie[p] = jl;
            }
        }
        __syncthreads();
        if (t == 0) {   // lowest-index ties (JAX stable top_k)
            int nt = min((int)sCnt[2], 64);
            int last = -1;
            for (int r = 0; r < need; ++r) {
                int best = 0x7FFFFFFF;
                for (int q = 0; q < nt; ++q) { int j = sTie[q]; if (j > last && j < best) best = j; }
                sSel[cLess + r] = best;
                last = best;
            }
        }
        __syncthreads();
        if (t < KNNK) {   // deterministic ascending-index order + mark selected
            int myj = sSel[t];
            int rank = 0;
#pragma unroll 4
            for (int q = 0; q < KNNK; ++q) rank += (sSel[q] < myj);
            g_src[i*EPN + rank] = base + myj;
            s_key[myj] = U_INV;
        }
        __syncthreads();
    }

    // ---- lr transform over same-chain domain + fused byte-3 histogram
#pragma unroll
    for (int c = 0; c < 8; ++c) s_hist[c][t] = 0;
    __syncthreads();
    for (int jl = t; jl < NL; jl += 256) {
        unsigned u = s_key[jl];
        unsigned outk = U_INV;
        if (u < U_INV) {
            float d2e = __fadd_rn(__uint_as_float(u), 1e-6f);
            float s = lr_key((unsigned)(i*NN + base + jl), d2e);
            outk = __float_as_uint(s);
            atomicAdd(&s_hist[w][outk >> 24], 1u);
        }
        s_key[jl] = outk;
    }
    __syncthreads();

    // ================= lr stage =================
    {
        uint2 rk = radix_select(s_key, s_hist, sScan, sCand, sCnt, LRKK, U_INV, t);
        const unsigned T = rk.x;
        const int need = (int)rk.y;
        const int cLess = LRKK - need;

        if (t == 0) { sCnt[1] = 0; sCnt[2] = 0; }
        __syncthreads();
        for (int jl = t; jl < NL; jl += 256) {
            unsigned u = s_key[jl];
            if (u < T) {
                int p = (int)atomicAdd(&sCnt[1], 1u);
                sSel[p] = jl;
            } else if (u == T) {
                int p = (int)atomicAdd(&sCnt[2], 1u);
                if (p < 64) sTie[p] = jl;
            }
        }
        __syncthreads();
        if (t == 0) {
            int nt = min((int)sCnt[2], 64);
            int last = -1;
            for (int r = 0; r < need; ++r) {
                int best = 0x7FFFFFFF;
                for (int q = 0; q < nt; ++q) { int j = sTie[q]; if (j > last && j < best) best = j; }
                sSel[cLess + r] = best;
                last = best;
            }
        }
        __syncthreads();
        if (t < LRKK) {
            int myj = sSel[t];
            int rank = 0;
#pragma unroll 4
            for (int q = 0; q < LRKK; ++q) rank += (sSel[q] < myj);
            g_src[i*EPN + KNNK + rank] = base + myj;
        }
    }
}

// ---------------- kernel 3: edge MLP (factorized; 8 edges per warp) ---------
__global__ __launch_bounds__(256) void edge_kernel(
    const float* __restrict__ w1,
    const float* __restrict__ w2, const float* __restrict__ b2)
{
    __shared__ float sW1eT[HC][36];
    __shared__ float sW2T[HEADS][36];
    __shared__ float sB2[HEADS];
    __shared__ float sEF[8][8][40];
    __shared__ float sH[8][8][40];
    const int t = threadIdx.x, lane = t & 31, warp = t >> 5;
    for (int idx = t; idx < HC*32; idx += 256) {
        int h = idx >> 5, c = idx & 31;
        sW1eT[h][c] = w1[(2*SPH + c)*HC + h];
    }
    for (int idx = t; idx < HEADS*32; idx += 256) {
        int h = idx >> 5, c = idx & 31;
        sW2T[h][c] = w2[c*HEADS + h];
    }
    if (t < HEADS) sB2[t] = b2[t];
    __syncthreads();

    const int e0 = blockIdx.x*EPB + warp*8;

    {
        const int e = lane >> 2, q = lane & 3;
        const int edge = e0 + e;
        const int ii = edge / EPN;
        const int ss = g_src[edge];
        float4 ps = g_xp[ss], pd = g_xp[ii];
        float dx = ps.x-pd.x, dy = ps.y-pd.y, dz = ps.z-pd.z;
        float dist = sqrtf(__fadd_rn(__fadd_rn(__fmul_rn(dx,dx),__fmul_rn(dy,dy)),__fmul_rn(dz,dz)));
        if (q < 2) {
#pragma unroll
            for (int r = 0; r < 8; ++r) {
                int f = q*8 + r;
                float mu = (float)f * (20.0f/15.0f);
                float zz = (dist - mu) * 0.8f;
                sEF[warp][e][f] = expf(-zz*zz);
            }
        } else {
            float dfl = (float)(ss - ii);
#pragma unroll
            for (int r = 0; r < 4; ++r) {
                int k = (q-2)*4 + r;
                float fr = expf((float)(2*k) * -0.5756462732485114f);
                float sv, cv;
                sincosf(dfl * fr, &sv, &cv);
                sEF[warp][e][16 + k] = cv;
                sEF[warp][e][24 + k] = sv;
            }
        }
    }
    __syncwarp();

    {
        float h[8];
#pragma unroll
        for (int e = 0; e < 8; ++e) {
            const int edge = e0 + e;
            const int ii = edge / EPN;
            const int ss = g_src[edge];
            h[e] = g_hsrc[ss*HC + lane] + g_hdst[ii*HC + lane];
        }
#pragma unroll
        for (int c4 = 0; c4 < 32; c4 += 4) {
            float4 w4 = *(const float4*)&sW1eT[lane][c4];
#pragma unroll
            for (int e = 0; e < 8; ++e) {
                float4 f4 = *(const float4*)&sEF[warp][e][c4];
                h[e] = __fmaf_rn(f4.x, w4.x, h[e]);
                h[e] = __fmaf_rn(f4.y, w4.y, h[e]);
                h[e] = __fmaf_rn(f4.z, w4.z, h[e]);
                h[e] = __fmaf_rn(f4.w, w4.w, h[e]);
            }
        }
#pragma unroll
        for (int e = 0; e < 8; ++e) {
            float hv = h[e];
            sH[warp][e][lane] = hv * (1.0f / (1.0f + expf(-hv)));
        }
    }
    __syncwarp();

    {
        const int e = lane >> 2;
        const int h0 = lane & 3, h1 = h0 + 4;
        float a0 = sB2[h0], a1 = sB2[h1];
#pragma unroll
        for (int c4 = 0; c4 < 32; c4 += 4) {
            float4 hv = *(const float4*)&sH[warp][e][c4];
            float4 wa = *(const float4*)&sW2T[h0][c4];
            float4 wb = *(const float4*)&sW2T[h1][c4];
            a0 = __fmaf_rn(hv.x, wa.x, a0); a1 = __fmaf_rn(hv.x, wb.x, a1);
            a0 = __fmaf_rn(hv.y, wa.y, a0); a1 = __fmaf_rn(hv.y, wb.y, a1);
            a0 = __fmaf_rn(hv.z, wa.z, a0); a1 = __fmaf_rn(hv.z, wb.z, a1);
            a0 = __fmaf_rn(hv.w, wa.w, a0); a1 = __fmaf_rn(hv.w, wb.w, a1);
        }
        g_logit[(e0+e)*HEADS + h0] = a0;
        g_logit[(e0+e)*HEADS + h1] = a1;
    }
}

// ---------------- kernel 4: softmax + aggregate + epilogues -----------------
__global__ __launch_bounds__(256) void agg_kernel(
    const float* __restrict__ X, const float* __restrict__ bbr,
    const int* __restrict__ noise,
    const float* __restrict__ wo,   const float* __restrict__ bo,
    const float* __restrict__ wg,   const float* __restrict__ bg,
    const float* __restrict__ wf,   const float* __restrict__ bf,
    const float* __restrict__ wxca,
    const float* __restrict__ wgate, const float* __restrict__ bgate,
    const float* __restrict__ wbb,
    float* __restrict__ out)
{
    __shared__ float sal[EPN*HEADS];
    __shared__ int   ssrc[EPN];
    __shared__ float spart[4][LL*HV];
    __shared__ float sagg[LL*HV];
    __shared__ float sout0[LL*BBC];
    __shared__ float soutf[LL*BBC];
    __shared__ float sgate[BBC];
    __shared__ float svec[3];
    __shared__ float sg2;
    __shared__ float subb[9];
    const int i = blockIdx.x;
    const int t = threadIdx.x;

    for (int idx = t; idx < EPN*HEADS; idx += 256) sal[idx] = g_logit[i*EPN*HEADS + idx];
    if (t < EPN) ssrc[t] = g_src[i*EPN + t];
    __syncthreads();

    if (t < 64) {
        const int h = t >> 3, sub = t & 7;
        float m = -3.4e38f;
        for (int e = sub; e < EPN; e += 8) m = fmaxf(m, sal[e*HEADS + h]);
#pragma unroll
        for (int o = 1; o < 8; o <<= 1) m = fmaxf(m, __shfl_xor_sync(0xffffffffu, m, o, 8));
        float Z = 0.f;
        for (int e = sub; e < EPN; e += 8) {
            float pp = expf(sal[e*HEADS + h] - m);
            sal[e*HEADS + h] = pp;
            Z += pp;
        }
#pragma unroll
        for (int o = 1; o < 8; o <<= 1) Z += __shfl_xor_sync(0xffffffffu, Z, o, 8);
        float inv = 1.0f / (Z + 1e-9f);
        for (int e = sub; e < EPN; e += 8) sal[e*HEADS + h] *= inv;
    }
    __syncthreads();

    // gather-aggregate from fp16 v (R12-proven form)
    {
        const int d = t & 63, g = t >> 6;
        float acc[LL];
#pragma unroll
        for (int l = 0; l < LL; ++l) acc[l] = 0.f;
        const int h = d >> 3;
        for (int e = g; e < EPN; e += 8) {
            const int e2 = e + 4;
            const bool has2 = (e2 < EPN);
            int s0 = ssrc[e];
            int s1 = has2 ? ssrc[e2] : s0;
            float al0 = sal[e*HEADS + h];
            float al1 = has2 ? sal[e2*HEADS + h] : 0.f;
            const __half2* p0 = g_vh + ((size_t)s0*HV + d)*5;
            const __half2* p1 = g_vh + ((size_t)s1*HV + d)*5;
#pragma unroll
            for (int k = 0; k < 4; ++k) {
                float2 f0 = __half22float2(p0[k]);
                float2 f1 = __half22float2(p1[k]);
                acc[2*k]   = __fmaf_rn(al0, f0.x, __fmaf_rn(al1, f1.x, acc[2*k]));
                acc[2*k+1] = __fmaf_rn(al0, f0.y, __fmaf_rn(al1, f1.y, acc[2*k+1]));
            }
            {
                float2 f0 = __half22float2(p0[4]);
                float2 f1 = __half22float2(p1[4]);
                acc[8] = __fmaf_rn(al0, f0.x, __fmaf_rn(al1, f1.x, acc[8]));
            }
        }
#pragma unroll
        for (int l = 0; l < LL; ++l) spart[g][l*HV + d] = acc[l];
    }
    __syncthreads();
    for (int idx = t; idx < LL*HV; idx += 256)
        sagg[idx] = ((spart[0][idx] + spart[1][idx]) + spart[2][idx]) + spart[3][idx];
    __syncthreads();

    for (int idx = t; idx < LL*BBC; idx += 256) {
        int l = idx >> 5, d = idx & 31;
        const float* w = wo + c_L3[l]*HV*BBC;
        float acc = 0.f;
#pragma unroll 8
        for (int c = 0; c < HV; ++c) acc = __fmaf_rn(sagg[l*HV + c], w[c*BBC + d], acc);
        if (l == 0) acc += bo[d];
        sout0[idx] = acc;
    }
    __syncthreads();

    if (t < BBC) {
        float g = 0.f;
        for (int c = 0; c < BBC; ++c) g = __fmaf_rn(sout0[c], wg[c*BBC + t], g);
        g += bg[t];
        sgate[t] = g * (1.0f / (1.0f + expf(-g)));
    }
    __syncthreads();

    for (int idx = t; idx < LL*BBC; idx += 256) {
        int l = idx >> 5, d = idx & 31;
        const float* w = wf + c_L3[l]*BBC*BBC;
        float acc = 0.f;
#pragma unroll 8
        for (int c = 0; c < BBC; ++c) acc = __fmaf_rn(sout0[l*BBC + c], w[c*BBC + d], acc);
        if (l == 0) acc += bf[d];
        float val = sout0[idx] + acc * sgate[d];
        soutf[idx] = val;
        out[OFF_OUT + (size_t)i*LL*BBC + idx] = val;
    }
    __syncthreads();

    if (t < 3) {
        float acc = 0.f;
        for (int c = 0; c < BBC; ++c) acc = __fmaf_rn(soutf[(1+t)*BBC + c], wxca[BBC + c], acc);
        svec[t] = acc;
    }
    if (t == 3) {
        float s = 0.f;
        for (int c = 0; c < BBC; ++c) s = __fmaf_rn(soutf[c], wgate[c], s);
        s += bgate[0];
        sg2 = fmaxf(s, 0.f) + log1pf(expf(-fabsf(s)));
    }
    if (t >= 8 && t < 17) {
        int idx = t - 8;
        int k = idx / 3, m = idx - 3*k;
        float acc = 0.f;
        for (int c = 0; c < BBC; ++c) acc = __fmaf_rn(soutf[(1+k)*BBC + c], wbb[(BBC + c)*NBB + m], acc);
        subb[idx] = acc;
    }
    __syncthreads();

    const int nz = noise[i];
    if (t < 3)
        out[(size_t)i*3 + t] = X[i*3+t] + (nz ? svec[t]*sg2 : 0.f);
    if (t >= 8 && t < 17) {
        int idx = t - 8;
        int m = idx / 3, k = idx - 3*m;
        out[OFF_BB + (size_t)i*9 + idx] = bbr[(size_t)i*9 + idx] + (nz ? subb[k*3 + m] : 0.f);
    }
}

// ---------------- launch ----------------------------------------------------
extern "C" void kernel_launch(void* const* d_in, const int* in_sizes, int n_in,
                              void* d_out, int out_size)
{
    const float* X      = (const float*)d_in[0];
    const float* bbr    = (const float*)d_in[1];
    const float* bbf    = (const float*)d_in[2];
    const int*   xmask  = (const int*)d_in[4];
    const int*   noise  = (const int*)d_in[5];
    const float* w1     = (const float*)d_in[6];
    const float* b1     = (const float*)d_in[7];
    const float* w2     = (const float*)d_in[8];
    const float* b2     = (const float*)d_in[9];
    const float* wv     = (const float*)d_in[10];
    const float* bv     = (const float*)d_in[11];
    const float* wo     = (const float*)d_in[12];
    const float* bo     = (const float*)d_in[13];
    const float* wg     = (const float*)d_in[14];
    const float* bg     = (const float*)d_in[15];
    const float* wf     = (const float*)d_in[16];
    const float* bf     = (const float*)d_in[17];
    const float* wxca   = (const float*)d_in[18];
    const float* wgate  = (const float*)d_in[20];
    const float* bgate  = (const float*)d_in[21];
    const float* wbb    = (const float*)d_in[22];
    float* out = (float*)d_out;

    node_v_kernel<<<NN/NVB, 512>>>(bbf, bbr, noise, xmask, X, wv, bv, w1, b1);
    row_kernel<<<NN, 256>>>(xmask);
    edge_kernel<<<NN*EPN/EPB, 256>>>(w1, w2, b2);
    agg_kernel<<<NN, 256>>>(X, bbr, noise, wo, bo, wg, bg, wf, bf,
                            wxca, wgate, bgate, wbb, out);
}

// round 16
// speedup vs baseline: 1.7754x; 1.0099x over previous
#include <cuda_runtime.h>
#include <cuda_fp16.h>
#include <math.h>

// ---------------- problem constants ----------------
#define NN    4096
#define NL    2048         // nodes per chain (batch = repeat(arange(2), 2048))
#define KNNK  20
#define LRKK  40
#define EPN   60
#define LL    9
#define SPH   35
#define BBC   32
#define NBB   3
#define HEADS 8
#define HV    64
#define HC    32
#define NVB   8
#define CAP   2048

#define OFF_BB  (NN*3)
#define OFF_OUT (NN*3 + NN*9)

__device__ int     g_src[NN*EPN];
__device__ float   g_inv[NN*SPH];
__device__ __half2 g_vh[NN*HV*5];   // [node][d][5 half2] (R12-proven layout)
__device__ float   g_hsrc[NN*HC];
__device__ float   g_hdst[NN*HC];
__device__ float4  g_xp[NN];        // [x,y,z,x2]; x2=+inf if x_mask

__constant__ int c_L3[LL] = {0,1,1,1,2,2,2,2,2};

// ---------------- threefry2x32 lr key (JAX partitionable path) --------------
__device__ __forceinline__ float lr_key(unsigned int idx, float d2e) {
    unsigned int x0 = 0u, x1 = idx;
    const unsigned int ks0 = 0u, ks1 = 1u, ks2 = 0x1BD11BDBu;
#define TFR(r) { x0 += x1; x1 = __funnelshift_l(x1, x1, (r)); x1 ^= x0; }
    x0 += ks0; x1 += ks1;
    TFR(13) TFR(15) TFR(26) TFR(6);  x0 += ks1; x1 += ks2 + 1u;
    TFR(17) TFR(29) TFR(16) TFR(24); x0 += ks2; x1 += ks0 + 2u;
    TFR(13) TFR(15) TFR(26) TFR(6);  x0 += ks0; x1 += ks1 + 3u;
    TFR(17) TFR(29) TFR(16) TFR(24); x0 += ks1; x1 += ks2 + 4u;
    TFR(13) TFR(15) TFR(26) TFR(6);  x0 += ks2; x1 += ks0 + 5u;
#undef TFR
    unsigned int bits = x0 ^ x1;
    float u = __uint_as_float((bits >> 9) | 0x3f800000u) - 1.0f;
    u = fmaxf(u, 1.17549435e-38f);
    float w = -__logf(u);
    return w * (d2e * __fsqrt_rn(d2e));
}

// ---------------- kernel 1: node features + V(fp16) + partials + xp ---------
__global__ __launch_bounds__(512) void node_v_kernel(
    const float* __restrict__ bbf, const float* __restrict__ bbr,
    const int* __restrict__ noise, const int* __restrict__ xmask,
    const float* __restrict__ X,
    const float* __restrict__ wv, const float* __restrict__ bv,
    const float* __restrict__ w1, const float* __restrict__ b1)
{
    __shared__ float sWV[3*SPH*HV];
    __shared__ float sW1[2*SPH*HC];
    __shared__ float nf[NVB][LL*SPH];
    const int t = threadIdx.x;
    for (int idx = t; idx < 3*SPH*HV; idx += 512) sWV[idx] = wv[idx];
    for (int idx = t; idx < 2*SPH*HC; idx += 512) sW1[idx] = w1[idx];

    const int g = t >> 6;
    const int tt = t & 63;
    const int i = blockIdx.x*NVB + g;

    for (int idx = tt; idx < LL*SPH; idx += 64) {
        int l = idx / SPH, c = idx - l*SPH;
        float v = 0.f;
        if (c < BBC)                    v = bbf[(i*LL + l)*BBC + c];
        else if (l >= 1 && l <= 3)      v = bbr[(i*NBB + (c-BBC))*3 + (l-1)];
        if (l == 0 && c == SPH-1)       v = noise[i] ? 1.0f : 0.0f;
        nf[g][idx] = v;
    }
    if (tt == 0) {
        float x = X[3*i], y = X[3*i+1], z = X[3*i+2];
        float x2 = __fadd_rn(__fadd_rn(__fmul_rn(x,x),__fmul_rn(y,y)),__fmul_rn(z,z));
        g_xp[i] = make_float4(x, y, z, xmask[i] ? __int_as_float(0x7F800000) : x2);
    }
    __syncthreads();
    if (tt < SPH) g_inv[i*SPH + tt] = nf[g][tt];

    if (tt < HC) {
        float acc = b1[tt];
#pragma unroll 7
        for (int c = 0; c < SPH; ++c) acc = __fmaf_rn(nf[g][c], sW1[c*HC + tt], acc);
        g_hsrc[i*HC + tt] = acc;
    } else {
        int d = tt - HC;
        float acc = 0.f;
#pragma unroll 7
        for (int c = 0; c < SPH; ++c) acc = __fmaf_rn(nf[g][c], sW1[(SPH + c)*HC + d], acc);
        g_hdst[i*HC + d] = acc;
    }

    {
        const int d = tt;
        float va[LL];
#pragma unroll
        for (int l = 0; l < LL; ++l) {
            const float* w = sWV + c_L3[l]*SPH*HV;
            float acc = 0.f;
#pragma unroll 7
            for (int c = 0; c < SPH; ++c) acc = __fmaf_rn(nf[g][l*SPH + c], w[c*HV + d], acc);
            if (l == 0) acc += bv[d];
            va[l] = acc;
        }
        __half2* dst = g_vh + ((size_t)i*HV + d)*5;
        dst[0] = __floats2half2_rn(va[0], va[1]);
        dst[1] = __floats2half2_rn(va[2], va[3]);
        dst[2] = __floats2half2_rn(va[4], va[5]);
        dst[3] = __floats2half2_rn(va[6], va[7]);
        dst[4] = __floats2half2_rn(va[8], 0.f);
    }
}

// ---------------- radix-select (2048-domain) --------------------------------
#define PICK(BYTE)                                                             \
    {                                                                          \
        unsigned cnt = 0;                                                      \
        _Pragma("unroll")                                                      \
        for (int c = 0; c < 8; ++c) cnt += hist[c][t];                         \
        unsigned v = cnt;                                                      \
        _Pragma("unroll")                                                      \
        for (int o = 1; o < 32; o <<= 1) {                                     \
            unsigned n = __shfl_up_sync(0xffffffffu, v, o);                    \
            if (lane >= o) v += n;                                             \
        }                                                                      \
        if (lane == 31) sScan[w] = v;                                          \
        __syncthreads();                                                       \
        if (t == 0) {                                                          \
            unsigned a = 0;                                                    \
            _Pragma("unroll")                                                  \
            for (int c = 0; c < 8; ++c) { unsigned x = sScan[c]; sScan[c] = a; a += x; } \
        }                                                                      \
        __syncthreads();                                                       \
        unsigned incl = v + sScan[w];                                          \
        unsigned excl = incl - cnt;                                            \
        if (kk > excl && kk <= incl) { sScan[8] = (unsigned)t; sScan[9] = excl; } \
        __syncthreads();                                                       \
        prefix |= sScan[8] << (8*(BYTE));                                      \
        kk -= sScan[9];                                                        \
        __syncthreads();                                                       \
    }

__device__ __forceinline__ uint2 radix_select(
    const unsigned* s_key, unsigned (*hist)[256], unsigned* sScan,
    unsigned short* cand, unsigned* sCnt,
    unsigned k, unsigned validMax, int t)
{
    const int lane = t & 31, w = t >> 5;
    unsigned prefix = 0, kk = k;

    PICK(3)

    if (t == 0) sCnt[0] = 0;
    __syncthreads();
    const unsigned b3 = prefix >> 24;
    for (int j = t; j < NL; j += 256) {
        unsigned u = s_key[j];
        if (u < validMax && (u >> 24) == b3) {
            unsigned p = atomicAdd(&sCnt[0], 1u);
            cand[p] = (unsigned short)j;
        }
    }
    __syncthreads();
    const int candN = (int)sCnt[0];

#pragma unroll
    for (int byte = 2; byte >= 0; --byte) {
        const unsigned maskHi = 0xFFFFFFFFu << (8*(byte+1));
#pragma unroll
        for (int c = 0; c < 8; ++c) hist[c][t] = 0;
        __syncthreads();
        for (int c = t; c < candN; c += 256) {
            unsigned u = s_key[cand[c]];
            if ((u & maskHi) == prefix)
                atomicAdd(&hist[w][(u >> (8*byte)) & 255u], 1u);
        }
        __syncthreads();
        PICK(byte)
    }
    return make_uint2(prefix, kk);
}

// ---------------- kernel 2: distances + knn top20 + lr top40 ---------------
__global__ __launch_bounds__(256) void row_kernel(
    const int* __restrict__ xmask)
{
    __shared__ unsigned s_key[NL];
    __shared__ unsigned s_hist[8][256];
    __shared__ unsigned sScan[10];
    __shared__ unsigned short sCand[CAP];
    __shared__ unsigned sCnt[4];
    __shared__ int      sSel[EPN];
    __shared__ int      sTie[64];
    const int i = blockIdx.x;
    const int t = threadIdx.x;
    const int w = t >> 5;
    const unsigned U_INV = __float_as_uint(1e30f);

    if (xmask[i] != 0) {
        for (int e = t; e < EPN; e += 256)
            g_src[i*EPN + e] = (e < KNNK) ? e : (e - KNNK);
        return;
    }

    const float4 pi = g_xp[i];
    const float xi = pi.x, yi = pi.y, zi = pi.z, x2i = pi.w;
    const int base = (i >> 11) << 11;
    const int iloc = i - base;

#pragma unroll
    for (int c = 0; c < 8; ++c) s_hist[c][t] = 0;
    __syncthreads();
    for (int jl = t; jl < NL; jl += 256) {
        float4 p = g_xp[base + jl];
        float dot = __fmul_rn(xi, p.x);
        dot = __fmaf_rn(yi, p.y, dot);
        dot = __fmaf_rn(zi, p.z, dot);
        float d2  = fmaxf(__fsub_rn(__fadd_rn(x2i, p.w), __fmul_rn(2.0f, dot)), 0.0f);
        unsigned u = (jl == iloc) ? U_INV : __float_as_uint(d2);
        s_key[jl] = u;
        if (u < U_INV) atomicAdd(&s_hist[w][u >> 24], 1u);
    }
    __syncthreads();

    // ================= knn stage =================
    {
        uint2 rk = radix_select(s_key, s_hist, sScan, sCand, sCnt, KNNK, U_INV, t);
        const unsigned T = rk.x;
        const int need = (int)rk.y;
        const int cLess = KNNK - need;

        if (t == 0) { sCnt[1] = 0; sCnt[2] = 0; }
        __syncthreads();
        for (int jl = t; jl < NL; jl += 256) {
            unsigned u = s_key[jl];
            if (u < T) {
                int p = (int)atomicAdd(&sCnt[1], 1u);
                sSel[p] = jl;
            } else if (u == T) {
                int p = (int)atomicAdd(&sCnt[2], 1u);
                if (p < 64) sTie[p] = jl;
            }
        }
        __syncthreads();
        if (t == 0) {
            int nt = min((int)sCnt[2], 64);
            int last = -1;
            for (int r = 0; r < need; ++r) {
                int best = 0x7FFFFFFF;
                for (int q = 0; q < nt; ++q) { int j = sTie[q]; if (j > last && j < best) best = j; }
                sSel[cLess + r] = best;
                last = best;
            }
        }
        __syncthreads();
        if (t < KNNK) {
            int myj = sSel[t];
            int rank = 0;
#pragma unroll 4
            for (int q = 0; q < KNNK; ++q) rank += (sSel[q] < myj);
            g_src[i*EPN + rank] = base + myj;
            s_key[myj] = U_INV;
        }
        __syncthreads();
    }

#pragma unroll
    for (int c = 0; c < 8; ++c) s_hist[c][t] = 0;
    __syncthreads();
    for (int jl = t; jl < NL; jl += 256) {
        unsigned u = s_key[jl];
        unsigned outk = U_INV;
        if (u < U_INV) {
            float d2e = __fadd_rn(__uint_as_float(u), 1e-6f);
            float s = lr_key((unsigned)(i*NN + base + jl), d2e);
            outk = __float_as_uint(s);
            atomicAdd(&s_hist[w][outk >> 24], 1u);
        }
        s_key[jl] = outk;
    }
    __syncthreads();

    // ================= lr stage =================
    {
        uint2 rk = radix_select(s_key, s_hist, sScan, sCand, sCnt, LRKK, U_INV, t);
        const unsigned T = rk.x;
        const int need = (int)rk.y;
        const int cLess = LRKK - need;

        if (t == 0) { sCnt[1] = 0; sCnt[2] = 0; }
        __syncthreads();
        for (int jl = t; jl < NL; jl += 256) {
            unsigned u = s_key[jl];
            if (u < T) {
                int p = (int)atomicAdd(&sCnt[1], 1u);
                sSel[p] = jl;
            } else if (u == T) {
                int p = (int)atomicAdd(&sCnt[2], 1u);
                if (p < 64) sTie[p] = jl;
            }
        }
        __syncthreads();
        if (t == 0) {
            int nt = min((int)sCnt[2], 64);
            int last = -1;
            for (int r = 0; r < need; ++r) {
                int best = 0x7FFFFFFF;
                for (int q = 0; q < nt; ++q) { int j = sTie[q]; if (j > last && j < best) best = j; }
                sSel[cLess + r] = best;
                last = best;
            }
        }
        __syncthreads();
        if (t < LRKK) {
            int myj = sSel[t];
            int rank = 0;
#pragma unroll 4
            for (int q = 0; q < LRKK; ++q) rank += (sSel[q] < myj);
            g_src[i*EPN + KNNK + rank] = base + myj;
        }
    }
}

// ---------------- kernel 3: FUSED edge MLP + softmax + aggregate + epilogue -
struct P1 {   // edge-MLP scratch
    float W1eT[HC][36];
    float W2T[HEADS][36];
    float EF[8][8][40];
    float Hh[8][8][40];
};
struct P2 {   // aggregate scratch
    float part[4][LL*HV];
    float agg[LL*HV];
    float out0[LL*BBC];
    float outf[LL*BBC];
};

__global__ __launch_bounds__(256) void agg_kernel(
    const float* __restrict__ X, const float* __restrict__ bbr,
    const int* __restrict__ noise,
    const float* __restrict__ w1,
    const float* __restrict__ w2,   const float* __restrict__ b2,
    const float* __restrict__ wo,   const float* __restrict__ bo,
    const float* __restrict__ wg,   const float* __restrict__ bg,
    const float* __restrict__ wf,   const float* __restrict__ bf,
    const float* __restrict__ wxca,
    const float* __restrict__ wgate, const float* __restrict__ bgate,
    const float* __restrict__ wbb,
    float* __restrict__ out)
{
    __shared__ union { P1 p1; P2 p2; } u;
    __shared__ float sal[EPN*HEADS];
    __shared__ int   ssrc[EPN];
    __shared__ float sB2[HEADS];
    __shared__ float sgate[BBC];
    __shared__ float svec[3];
    __shared__ float sg2;
    __shared__ float subb[9];
    const int i = blockIdx.x;
    const int t = threadIdx.x;
    const int lane = t & 31, warp = t >> 5;

    if (t < EPN) ssrc[t] = g_src[i*EPN + t];
    if (t < HEADS) sB2[t] = b2[t];
    for (int idx = t; idx < HC*32; idx += 256) {
        int h = idx >> 5, c = idx & 31;
        u.p1.W1eT[h][c] = w1[(2*SPH + c)*HC + h];
    }
    for (int idx = t; idx < HEADS*32; idx += 256) {
        int h = idx >> 5, c = idx & 31;
        u.p1.W2T[h][c] = w2[c*HEADS + h];
    }
    __syncthreads();

    // ---- edge MLP stage A: features (4 lanes per edge; warp w owns edges w*8..w*8+7)
    {
        const int e = lane >> 2, q = lane & 3;
        const int ew = warp*8 + e;
        if (ew < EPN) {
            const int ss = ssrc[ew];
            float4 ps = g_xp[ss], pd = g_xp[i];
            float dx = ps.x-pd.x, dy = ps.y-pd.y, dz = ps.z-pd.z;
            float dist = sqrtf(__fadd_rn(__fadd_rn(__fmul_rn(dx,dx),__fmul_rn(dy,dy)),__fmul_rn(dz,dz)));
            if (q < 2) {
#pragma unroll
                for (int r = 0; r < 8; ++r) {
                    int f = q*8 + r;
                    float mu = (float)f * (20.0f/15.0f);
                    float zz = (dist - mu) * 0.8f;
                    u.p1.EF[warp][e][f] = expf(-zz*zz);
                }
            } else {
                float dfl = (float)(ss - i);
#pragma unroll
                for (int r = 0; r < 4; ++r) {
                    int k = (q-2)*4 + r;
                    float fr = expf((float)(2*k) * -0.5756462732485114f);
                    float sv, cv;
                    sincosf(dfl * fr, &sv, &cv);
                    u.p1.EF[warp][e][16 + k] = cv;
                    u.p1.EF[warp][e][24 + k] = sv;
                }
            }
        }
    }
    __syncwarp();

    // ---- stage B: hidden units (lane = hidden unit; 8 edges in regs)
    {
        const float hd = g_hdst[i*HC + lane];
        float h[8];
#pragma unroll
        for (int e = 0; e < 8; ++e) {
            const int ew = warp*8 + e;
            h[e] = (ew < EPN) ? (g_hsrc[ssrc[ew]*HC + lane] + hd) : 0.f;
        }
#pragma unroll
        for (int c4 = 0; c4 < 32; c4 += 4) {
            float4 w4 = *(const float4*)&u.p1.W1eT[lane][c4];
#pragma unroll
            for (int e = 0; e < 8; ++e) {
                float4 f4 = *(const float4*)&u.p1.EF[warp][e][c4];
                h[e] = __fmaf_rn(f4.x, w4.x, h[e]);
                h[e] = __fmaf_rn(f4.y, w4.y, h[e]);
                h[e] = __fmaf_rn(f4.z, w4.z, h[e]);
                h[e] = __fmaf_rn(f4.w, w4.w, h[e]);
            }
        }
#pragma unroll
        for (int e = 0; e < 8; ++e) {
            if (warp*8 + e < EPN) {
                float hv = h[e];
                u.p1.Hh[warp][e][lane] = hv * (1.0f / (1.0f + expf(-hv)));
            }
        }
    }
    __syncwarp();

    // ---- stage C: logits -> sal
    {
        const int e = lane >> 2;
        const int ew = warp*8 + e;
        if (ew < EPN) {
            const int h0 = lane & 3, h1 = h0 + 4;
            float a0 = sB2[h0], a1 = sB2[h1];
#pragma unroll
            for (int c4 = 0; c4 < 32; c4 += 4) {
                float4 hv = *(const float4*)&u.p1.Hh[warp][e][c4];
                float4 wa = *(const float4*)&u.p1.W2T[h0][c4];
                float4 wb = *(const float4*)&u.p1.W2T[h1][c4];
                a0 = __fmaf_rn(hv.x, wa.x, a0); a1 = __fmaf_rn(hv.x, wb.x, a1);
                a0 = __fmaf_rn(hv.y, wa.y, a0); a1 = __fmaf_rn(hv.y, wb.y, a1);
                a0 = __fmaf_rn(hv.z, wa.z, a0); a1 = __fmaf_rn(hv.z, wb.z, a1);
                a0 = __fmaf_rn(hv.w, wa.w, a0); a1 = __fmaf_rn(hv.w, wb.w, a1);
            }
            sal[ew*HEADS + h0] = a0;
            sal[ew*HEADS + h1] = a1;
        }
    }
    __syncthreads();

    // ---- softmax per head (8 threads per head)
    if (t < 64) {
        const int h = t >> 3, sub = t & 7;
        float m = -3.4e38f;
        for (int e = sub; e < EPN; e += 8) m = fmaxf(m, sal[e*HEADS + h]);
#pragma unroll
        for (int o = 1; o < 8; o <<= 1) m = fmaxf(m, __shfl_xor_sync(0xffffffffu, m, o, 8));
        float Z = 0.f;
        for (int e = sub; e < EPN; e += 8) {
            float pp = expf(sal[e*HEADS + h] - m);
            sal[e*HEADS + h] = pp;
            Z += pp;
        }
#pragma unroll
        for (int o = 1; o < 8; o <<= 1) Z += __shfl_xor_sync(0xffffffffu, Z, o, 8);
        float inv = 1.0f / (Z + 1e-9f);
        for (int e = sub; e < EPN; e += 8) sal[e*HEADS + h] *= inv;
    }
    __syncthreads();

    // ---- gather-aggregate from fp16 v (R12-proven form); writes u.p2
    {
        const int d = t & 63, g = t >> 6;
        float acc[LL];
#pragma unroll
        for (int l = 0; l < LL; ++l) acc[l] = 0.f;
        const int h = d >> 3;
        for (int e = g; e < EPN; e += 8) {
            const int e2 = e + 4;
            const bool has2 = (e2 < EPN);
            int s0 = ssrc[e];
            int s1 = has2 ? ssrc[e2] : s0;
            float al0 = sal[e*HEADS + h];
            float al1 = has2 ? sal[e2*HEADS + h] : 0.f;
            const __half2* p0 = g_vh + ((size_t)s0*HV + d)*5;
            const __half2* p1 = g_vh + ((size_t)s1*HV + d)*5;
#pragma unroll
            for (int k = 0; k < 4; ++k) {
                float2 f0 = __half22float2(p0[k]);
                float2 f1 = __half22float2(p1[k]);
                acc[2*k]   = __fmaf_rn(al0, f0.x, __fmaf_rn(al1, f1.x, acc[2*k]));
                acc[2*k+1] = __fmaf_rn(al0, f0.y, __fmaf_rn(al1, f1.y, acc[2*k+1]));
            }
            {
                float2 f0 = __half22float2(p0[4]);
                float2 f1 = __half22float2(p1[4]);
                acc[8] = __fmaf_rn(al0, f0.x, __fmaf_rn(al1, f1.x, acc[8]));
            }
        }
#pragma unroll
        for (int l = 0; l < LL; ++l) u.p2.part[g][l*HV + d] = acc[l];
    }
    __syncthreads();
    for (int idx = t; idx < LL*HV; idx += 256)
        u.p2.agg[idx] = ((u.p2.part[0][idx] + u.p2.part[1][idx]) + u.p2.part[2][idx]) + u.p2.part[3][idx];
    __syncthreads();

    for (int idx = t; idx < LL*BBC; idx += 256) {
        int l = idx >> 5, d = idx & 31;
        const float* w = wo + c_L3[l]*HV*BBC;
        float acc = 0.f;
#pragma unroll 8
        for (int c = 0; c < HV; ++c) acc = __fmaf_rn(u.p2.agg[l*HV + c], w[c*BBC + d], acc);
        if (l == 0) acc += bo[d];
        u.p2.out0[idx] = acc;
    }
    __syncthreads();

    if (t < BBC) {
        float g = 0.f;
        for (int c = 0; c < BBC; ++c) g = __fmaf_rn(u.p2.out0[c], wg[c*BBC + t], g);
        g += bg[t];
        sgate[t] = g * (1.0f / (1.0f + expf(-g)));
    }
    __syncthreads();

    for (int idx = t; idx < LL*BBC; idx += 256) {
        int l = idx >> 5, d = idx & 31;
        const float* w = wf + c_L3[l]*BBC*BBC;
        float acc = 0.f;
#pragma unroll 8
        for (int c = 0; c < BBC; ++c) acc = __fmaf_rn(u.p2.out0[l*BBC + c], w[c*BBC + d], acc);
        if (l == 0) acc += bf[d];
        float val = u.p2.out0[idx] + acc * sgate[d];
        u.p2.outf[idx] = val;
        out[OFF_OUT + (size_t)i*LL*BBC + idx] = val;
    }
    __syncthreads();

    if (t < 3) {
        float acc = 0.f;
        for (int c = 0; c < BBC; ++c) acc = __fmaf_rn(u.p2.outf[(1+t)*BBC + c], wxca[BBC + c], acc);
        svec[t] = acc;
    }
    if (t == 3) {
        float s = 0.f;
        for (int c = 0; c < BBC; ++c) s = __fmaf_rn(u.p2.outf[c], wgate[c], s);
        s += bgate[0];
        sg2 = fmaxf(s, 0.f) + log1pf(expf(-fabsf(s)));
    }
    if (t >= 8 && t < 17) {
        int idx = t - 8;
        int k = idx / 3, m = idx - 3*k;
        float acc = 0.f;
        for (int c = 0; c < BBC; ++c) acc = __fmaf_rn(u.p2.outf[(1+k)*BBC + c], wbb[(BBC + c)*NBB + m], acc);
        subb[idx] = acc;
    }
    __syncthreads();

    const int nz = noise[i];
    if (t < 3)
        out[(size_t)i*3 + t] = X[i*3+t] + (nz ? svec[t]*sg2 : 0.f);
    if (t >= 8 && t < 17) {
        int idx = t - 8;
        int m = idx / 3, k = idx - 3*m;
        out[OFF_BB + (size_t)i*9 + idx] = bbr[(size_t)i*9 + idx] + (nz ? subb[k*3 + m] : 0.f);
    }
}

// ---------------- launch ----------------------------------------------------
extern "C" void kernel_launch(void* const* d_in, const int* in_sizes, int n_in,
                              void* d_out, int out_size)
{
    const float* X      = (const float*)d_in[0];
    const float* bbr    = (const float*)d_in[1];
    const float* bbf    = (const float*)d_in[2];
    const int*   xmask  = (const int*)d_in[4];
    const int*   noise  = (const int*)d_in[5];
    const float* w1     = (const float*)d_in[6];
    const float* b1     = (const float*)d_in[7];
    const float* w2     = (const float*)d_in[8];
    const float* b2     = (const float*)d_in[9];
    const float* wv     = (const float*)d_in[10];
    const float* bv     = (const float*)d_in[11];
    const float* wo     = (const float*)d_in[12];
    const float* bo     = (const float*)d_in[13];
    const float* wg     = (const float*)d_in[14];
    const float* bg     = (const float*)d_in[15];
    const float* wf     = (const float*)d_in[16];
    const float* bf     = (const float*)d_in[17];
    const float* wxca   = (const float*)d_in[18];
    const float* wgate  = (const float*)d_in[20];
    const float* bgate  = (const float*)d_in[21];
    const float* wbb    = (const float*)d_in[22];
    float* out = (float*)d_out;

    node_v_kernel<<<NN/NVB, 512>>>(bbf, bbr, noise, xmask, X, wv, bv, w1, b1);
    row_kernel<<<NN, 256>>>(xmask);
    agg_kernel<<<NN, 256>>>(X, bbr, noise, w1, w2, b2, wo, bo, wg, bg, wf, bf,
                            wxca, wgate, bgate, wbb, out);
}

// round 17
// speedup vs baseline: 1.8216x; 1.0260x over previous
#include <cuda_runtime.h>
#include <cuda_fp16.h>
#include <math.h>

// ---------------- problem constants ----------------
#define NN    4096
#define NL    2048         // nodes per chain (batch = repeat(arange(2), 2048))
#define KNNK  20
#define LRKK  40
#define EPN   60
#define LL    9
#define SPH   35
#define BBC   32
#define NBB   3
#define HEADS 8
#define HV    64
#define HC    32
#define NVB   8
#define CAP   2048

#define OFF_BB  (NN*3)
#define OFF_OUT (NN*3 + NN*9)

__device__ int     g_src[NN*EPN];
__device__ float   g_inv[NN*SPH];
__device__ __half2 g_vh[NN*HV*5];   // [node][d][5 half2] (R12-proven layout)
__device__ float   g_hsrc[NN*HC];
__device__ float   g_hdst[NN*HC];
__device__ float4  g_xp[NN];        // [x,y,z,x2]; x2=+inf if x_mask

__constant__ int c_L3[LL] = {0,1,1,1,2,2,2,2,2};

// ---------------- threefry2x32 lr key (JAX partitionable path) --------------
__device__ __forceinline__ float lr_key(unsigned int idx, float d2e) {
    unsigned int x0 = 0u, x1 = idx;
    const unsigned int ks0 = 0u, ks1 = 1u, ks2 = 0x1BD11BDBu;
#define TFR(r) { x0 += x1; x1 = __funnelshift_l(x1, x1, (r)); x1 ^= x0; }
    x0 += ks0; x1 += ks1;
    TFR(13) TFR(15) TFR(26) TFR(6);  x0 += ks1; x1 += ks2 + 1u;
    TFR(17) TFR(29) TFR(16) TFR(24); x0 += ks2; x1 += ks0 + 2u;
    TFR(13) TFR(15) TFR(26) TFR(6);  x0 += ks0; x1 += ks1 + 3u;
    TFR(17) TFR(29) TFR(16) TFR(24); x0 += ks1; x1 += ks2 + 4u;
    TFR(13) TFR(15) TFR(26) TFR(6);  x0 += ks2; x1 += ks0 + 5u;
#undef TFR
    unsigned int bits = x0 ^ x1;
    float u = __uint_as_float((bits >> 9) | 0x3f800000u) - 1.0f;
    u = fmaxf(u, 1.17549435e-38f);
    float w = -__logf(u);
    return w * (d2e * __fsqrt_rn(d2e));
}

// ---------------- kernel 1: node features + V(fp16) + partials + xp ---------
__global__ __launch_bounds__(512) void node_v_kernel(
    const float* __restrict__ bbf, const float* __restrict__ bbr,
    const int* __restrict__ noise, const int* __restrict__ xmask,
    const float* __restrict__ X,
    const float* __restrict__ wv, const float* __restrict__ bv,
    const float* __restrict__ w1, const float* __restrict__ b1)
{
    __shared__ float sWV[3*SPH*HV];
    __shared__ float sW1[2*SPH*HC];
    __shared__ float nf[NVB][LL*SPH];
    const int t = threadIdx.x;
    for (int idx = t; idx < 3*SPH*HV; idx += 512) sWV[idx] = wv[idx];
    for (int idx = t; idx < 2*SPH*HC; idx += 512) sW1[idx] = w1[idx];

    const int g = t >> 6;
    const int tt = t & 63;
    const int i = blockIdx.x*NVB + g;

    for (int idx = tt; idx < LL*SPH; idx += 64) {
        int l = idx / SPH, c = idx - l*SPH;
        float v = 0.f;
        if (c < BBC)                    v = bbf[(i*LL + l)*BBC + c];
        else if (l >= 1 && l <= 3)      v = bbr[(i*NBB + (c-BBC))*3 + (l-1)];
        if (l == 0 && c == SPH-1)       v = noise[i] ? 1.0f : 0.0f;
        nf[g][idx] = v;
    }
    if (tt == 0) {
        float x = X[3*i], y = X[3*i+1], z = X[3*i+2];
        float x2 = __fadd_rn(__fadd_rn(__fmul_rn(x,x),__fmul_rn(y,y)),__fmul_rn(z,z));
        g_xp[i] = make_float4(x, y, z, xmask[i] ? __int_as_float(0x7F800000) : x2);
    }
    __syncthreads();
    if (tt < SPH) g_inv[i*SPH + tt] = nf[g][tt];

    if (tt < HC) {
        float acc = b1[tt];
#pragma unroll 7
        for (int c = 0; c < SPH; ++c) acc = __fmaf_rn(nf[g][c], sW1[c*HC + tt], acc);
        g_hsrc[i*HC + tt] = acc;
    } else {
        int d = tt - HC;
        float acc = 0.f;
#pragma unroll 7
        for (int c = 0; c < SPH; ++c) acc = __fmaf_rn(nf[g][c], sW1[(SPH + c)*HC + d], acc);
        g_hdst[i*HC + d] = acc;
    }

    // V = so3_linear: c-outer / l-inner (3 shared weight LDS per c, 9 indep acc)
    {
        const int d = tt;
        float va[LL];
#pragma unroll
        for (int l = 0; l < LL; ++l) va[l] = 0.f;
        const float* nfg = nf[g];
#pragma unroll
        for (int c = 0; c < SPH; ++c) {
            float w0 = sWV[c*HV + d];
            float w1v = sWV[(SPH + c)*HV + d];
            float w2v = sWV[(2*SPH + c)*HV + d];
            va[0] = __fmaf_rn(nfg[c],         w0,  va[0]);
            va[1] = __fmaf_rn(nfg[SPH + c],   w1v, va[1]);
            va[2] = __fmaf_rn(nfg[2*SPH + c], w1v, va[2]);
            va[3] = __fmaf_rn(nfg[3*SPH + c], w1v, va[3]);
            va[4] = __fmaf_rn(nfg[4*SPH + c], w2v, va[4]);
            va[5] = __fmaf_rn(nfg[5*SPH + c], w2v, va[5]);
            va[6] = __fmaf_rn(nfg[6*SPH + c], w2v, va[6]);
            va[7] = __fmaf_rn(nfg[7*SPH + c], w2v, va[7]);
            va[8] = __fmaf_rn(nfg[8*SPH + c], w2v, va[8]);
        }
        va[0] += bv[d];
        __half2* dst = g_vh + ((size_t)i*HV + d)*5;
        dst[0] = __floats2half2_rn(va[0], va[1]);
        dst[1] = __floats2half2_rn(va[2], va[3]);
        dst[2] = __floats2half2_rn(va[4], va[5]);
        dst[3] = __floats2half2_rn(va[6], va[7]);
        dst[4] = __floats2half2_rn(va[8], 0.f);
    }
}

// ---------------- radix-select (2048-domain) --------------------------------
#define PICK(BYTE)                                                             \
    {                                                                          \
        unsigned cnt = 0;                                                      \
        _Pragma("unroll")                                                      \
        for (int c = 0; c < 8; ++c) cnt += hist[c][t];                         \
        unsigned v = cnt;                                                      \
        _Pragma("unroll")                                                      \
        for (int o = 1; o < 32; o <<= 1) {                                     \
            unsigned n = __shfl_up_sync(0xffffffffu, v, o);                    \
            if (lane >= o) v += n;                                             \
        }                                                                      \
        if (lane == 31) sScan[w] = v;                                          \
        __syncthreads();                                                       \
        if (t == 0) {                                                          \
            unsigned a = 0;                                                    \
            _Pragma("unroll")                                                  \
            for (int c = 0; c < 8; ++c) { unsigned x = sScan[c]; sScan[c] = a; a += x; } \
        }                                                                      \
        __syncthreads();                                                       \
        unsigned incl = v + sScan[w];                                          \
        unsigned excl = incl - cnt;                                            \
        if (kk > excl && kk <= incl) { sScan[8] = (unsigned)t; sScan[9] = excl; } \
        __syncthreads();                                                       \
        prefix |= sScan[8] << (8*(BYTE));                                      \
        kk -= sScan[9];                                                        \
        __syncthreads();                                                       \
    }

__device__ __forceinline__ uint2 radix_select(
    const unsigned* s_key, unsigned (*hist)[256], unsigned* sScan,
    unsigned short* cand, unsigned* sCnt,
    unsigned k, unsigned validMax, int t)
{
    const int lane = t & 31, w = t >> 5;
    unsigned prefix = 0, kk = k;

    PICK(3)

    if (t == 0) sCnt[0] = 0;
    __syncthreads();
    const unsigned b3 = prefix >> 24;
    for (int j = t; j < NL; j += 256) {
        unsigned u = s_key[j];
        if (u < validMax && (u >> 24) == b3) {
            unsigned p = atomicAdd(&sCnt[0], 1u);
            cand[p] = (unsigned short)j;
        }
    }
    __syncthreads();
    const int candN = (int)sCnt[0];

#pragma unroll
    for (int byte = 2; byte >= 0; --byte) {
        const unsigned maskHi = 0xFFFFFFFFu << (8*(byte+1));
#pragma unroll
        for (int c = 0; c < 8; ++c) hist[c][t] = 0;
        __syncthreads();
        for (int c = t; c < candN; c += 256) {
            unsigned u = s_key[cand[c]];
            if ((u & maskHi) == prefix)
                atomicAdd(&hist[w][(u >> (8*byte)) & 255u], 1u);
        }
        __syncthreads();
        PICK(byte)
    }
    return make_uint2(prefix, kk);
}

// ---------------- kernel 2: distances + knn top20 + lr top40 ---------------
__global__ __launch_bounds__(256) void row_kernel(
    const int* __restrict__ xmask)
{
    __shared__ unsigned s_key[NL];
    __shared__ unsigned s_hist[8][256];
    __shared__ unsigned sScan[10];
    __shared__ unsigned short sCand[CAP];
    __shared__ unsigned sCnt[4];
    __shared__ int      sSel[EPN];
    __shared__ int      sTie[64];
    const int i = blockIdx.x;
    const int t = threadIdx.x;
    const int w = t >> 5;
    const unsigned U_INV = __float_as_uint(1e30f);

    if (xmask[i] != 0) {
        for (int e = t; e < EPN; e += 256)
            g_src[i*EPN + e] = (e < KNNK) ? e : (e - KNNK);
        return;
    }

    const float4 pi = g_xp[i];
    const float xi = pi.x, yi = pi.y, zi = pi.z, x2i = pi.w;
    const int base = (i >> 11) << 11;
    const int iloc = i - base;

#pragma unroll
    for (int c = 0; c < 8; ++c) s_hist[c][t] = 0;
    __syncthreads();
    for (int jl = t; jl < NL; jl += 256) {
        float4 p = g_xp[base + jl];
        float dot = __fmul_rn(xi, p.x);
        dot = __fmaf_rn(yi, p.y, dot);
        dot = __fmaf_rn(zi, p.z, dot);
        float d2  = fmaxf(__fsub_rn(__fadd_rn(x2i, p.w), __fmul_rn(2.0f, dot)), 0.0f);
        unsigned u = (jl == iloc) ? U_INV : __float_as_uint(d2);
        s_key[jl] = u;
        if (u < U_INV) atomicAdd(&s_hist[w][u >> 24], 1u);
    }
    __syncthreads();

    // ================= knn stage =================
    {
        uint2 rk = radix_select(s_key, s_hist, sScan, sCand, sCnt, KNNK, U_INV, t);
        const unsigned T = rk.x;
        const int need = (int)rk.y;
        const int cLess = KNNK - need;

        if (t == 0) { sCnt[1] = 0; sCnt[2] = 0; }
        __syncthreads();
        for (int jl = t; jl < NL; jl += 256) {
            unsigned u = s_key[jl];
            if (u < T) {
                int p = (int)atomicAdd(&sCnt[1], 1u);
                sSel[p] = jl;
            } else if (u == T) {
                int p = (int)atomicAdd(&sCnt[2], 1u);
                if (p < 64) sTie[p] = jl;
            }
        }
        __syncthreads();
        if (t == 0) {
            int nt = min((int)sCnt[2], 64);
            int last = -1;
            for (int r = 0; r < need; ++r) {
                int best = 0x7FFFFFFF;
                for (int q = 0; q < nt; ++q) { int j = sTie[q]; if (j > last && j < best) best = j; }
                sSel[cLess + r] = best;
                last = best;
            }
        }
        __syncthreads();
        if (t < KNNK) {
            int myj = sSel[t];
            int rank = 0;
#pragma unroll 4
            for (int q = 0; q < KNNK; ++q) rank += (sSel[q] < myj);
            g_src[i*EPN + rank] = base + myj;
            s_key[myj] = U_INV;
        }
        __syncthreads();
    }

#pragma unroll
    for (int c = 0; c < 8; ++c) s_hist[c][t] = 0;
    __syncthreads();
    for (int jl = t; jl < NL; jl += 256) {
        unsigned u = s_key[jl];
        unsigned outk = U_INV;
        if (u < U_INV) {
            float d2e = __fadd_rn(__uint_as_float(u), 1e-6f);
            float s = lr_key((unsigned)(i*NN + base + jl), d2e);
            outk = __float_as_uint(s);
            atomicAdd(&s_hist[w][outk >> 24], 1u);
        }
        s_key[jl] = outk;
    }
    __syncthreads();

    // ================= lr stage =================
    {
        uint2 rk = radix_select(s_key, s_hist, sScan, sCand, sCnt, LRKK, U_INV, t);
        const unsigned T = rk.x;
        const int need = (int)rk.y;
        const int cLess = LRKK - need;

        if (t == 0) { sCnt[1] = 0; sCnt[2] = 0; }
        __syncthreads();
        for (int jl = t; jl < NL; jl += 256) {
            unsigned u = s_key[jl];
            if (u < T) {
                int p = (int)atomicAdd(&sCnt[1], 1u);
                sSel[p] = jl;
            } else if (u == T) {
                int p = (int)atomicAdd(&sCnt[2], 1u);
                if (p < 64) sTie[p] = jl;
            }
        }
        __syncthreads();
        if (t == 0) {
            int nt = min((int)sCnt[2], 64);
            int last = -1;
            for (int r = 0; r < need; ++r) {
                int best = 0x7FFFFFFF;
                for (int q = 0; q < nt; ++q) { int j = sTie[q]; if (j > last && j < best) best = j; }
                sSel[cLess + r] = best;
                last = best;
            }
        }
        __syncthreads();
        if (t < LRKK) {
            int myj = sSel[t];
            int rank = 0;
#pragma unroll 4
            for (int q = 0; q < LRKK; ++q) rank += (sSel[q] < myj);
            g_src[i*EPN + KNNK + rank] = base + myj;
        }
    }
}

// ---------------- kernel 3: FUSED edge MLP + softmax + aggregate + epilogue -
struct P1 {   // edge-MLP scratch
    float W1eT[HC][36];
    float W2T[HEADS][36];
    float EF[8][8][40];
    float Hh[8][8][40];
};
struct P2 {   // aggregate scratch
    float part[4][LL*HV];
    float agg[LL*HV];
    float out0[LL*BBC];
    float outf[LL*BBC];
};

__global__ __launch_bounds__(256) void agg_kernel(
    const float* __restrict__ X, const float* __restrict__ bbr,
    const int* __restrict__ noise,
    const float* __restrict__ w1,
    const float* __restrict__ w2,   const float* __restrict__ b2,
    const float* __restrict__ wo,   const float* __restrict__ bo,
    const float* __restrict__ wg,   const float* __restrict__ bg,
    const float* __restrict__ wf,   const float* __restrict__ bf,
    const float* __restrict__ wxca,
    const float* __restrict__ wgate, const float* __restrict__ bgate,
    const float* __restrict__ wbb,
    float* __restrict__ out)
{
    __shared__ union { P1 p1; P2 p2; } u;
    __shared__ float sal[EPN*HEADS];
    __shared__ int   ssrc[EPN];
    __shared__ float sB2[HEADS];
    __shared__ float sgate[BBC];
    __shared__ float svec[3];
    __shared__ float sg2;
    __shared__ float subb[9];
    const int i = blockIdx.x;
    const int t = threadIdx.x;
    const int lane = t & 31, warp = t >> 5;

    if (t < EPN) ssrc[t] = g_src[i*EPN + t];
    if (t < HEADS) sB2[t] = b2[t];
    for (int idx = t; idx < HC*32; idx += 256) {
        int h = idx >> 5, c = idx & 31;
        u.p1.W1eT[h][c] = w1[(2*SPH + c)*HC + h];
    }
    for (int idx = t; idx < HEADS*32; idx += 256) {
        int h = idx >> 5, c = idx & 31;
        u.p1.W2T[h][c] = w2[c*HEADS + h];
    }
    __syncthreads();

    // ---- edge MLP stage A: features
    {
        const int e = lane >> 2, q = lane & 3;
        const int ew = warp*8 + e;
        if (ew < EPN) {
            const int ss = ssrc[ew];
            float4 ps = g_xp[ss], pd = g_xp[i];
            float dx = ps.x-pd.x, dy = ps.y-pd.y, dz = ps.z-pd.z;
            float dist = sqrtf(__fadd_rn(__fadd_rn(__fmul_rn(dx,dx),__fmul_rn(dy,dy)),__fmul_rn(dz,dz)));
            if (q < 2) {
#pragma unroll
                for (int r = 0; r < 8; ++r) {
                    int f = q*8 + r;
                    float mu = (float)f * (20.0f/15.0f);
                    float zz = (dist - mu) * 0.8f;
                    u.p1.EF[warp][e][f] = expf(-zz*zz);
                }
            } else {
                float dfl = (float)(ss - i);
#pragma unroll
                for (int r = 0; r < 4; ++r) {
                    int k = (q-2)*4 + r;
                    float fr = expf((float)(2*k) * -0.5756462732485114f);
                    float sv, cv;
                    sincosf(dfl * fr, &sv, &cv);
                    u.p1.EF[warp][e][16 + k] = cv;
                    u.p1.EF[warp][e][24 + k] = sv;
                }
            }
        }
    }
    __syncwarp();

    // ---- stage B: hidden units
    {
        const float hd = g_hdst[i*HC + lane];
        float h[8];
#pragma unroll
        for (int e = 0; e < 8; ++e) {
            const int ew = warp*8 + e;
            h[e] = (ew < EPN) ? (g_hsrc[ssrc[ew]*HC + lane] + hd) : 0.f;
        }
#pragma unroll
        for (int c4 = 0; c4 < 32; c4 += 4) {
            float4 w4 = *(const float4*)&u.p1.W1eT[lane][c4];
#pragma unroll
            for (int e = 0; e < 8; ++e) {
                float4 f4 = *(const float4*)&u.p1.EF[warp][e][c4];
                h[e] = __fmaf_rn(f4.x, w4.x, h[e]);
                h[e] = __fmaf_rn(f4.y, w4.y, h[e]);
                h[e] = __fmaf_rn(f4.z, w4.z, h[e]);
                h[e] = __fmaf_rn(f4.w, w4.w, h[e]);
            }
        }
#pragma unroll
        for (int e = 0; e < 8; ++e) {
            if (warp*8 + e < EPN) {
                float hv = h[e];
                u.p1.Hh[warp][e][lane] = hv * (1.0f / (1.0f + expf(-hv)));
            }
        }
    }
    __syncwarp();

    // ---- stage C: logits -> sal
    {
        const int e = lane >> 2;
        const int ew = warp*8 + e;
        if (ew < EPN) {
            const int h0 = lane & 3, h1 = h0 + 4;
            float a0 = sB2[h0], a1 = sB2[h1];
#pragma unroll
            for (int c4 = 0; c4 < 32; c4 += 4) {
                float4 hv = *(const float4*)&u.p1.Hh[warp][e][c4];
                float4 wa = *(const float4*)&u.p1.W2T[h0][c4];
                float4 wb = *(const float4*)&u.p1.W2T[h1][c4];
                a0 = __fmaf_rn(hv.x, wa.x, a0); a1 = __fmaf_rn(hv.x, wb.x, a1);
                a0 = __fmaf_rn(hv.y, wa.y, a0); a1 = __fmaf_rn(hv.y, wb.y, a1);
                a0 = __fmaf_rn(hv.z, wa.z, a0); a1 = __fmaf_rn(hv.z, wb.z, a1);
                a0 = __fmaf_rn(hv.w, wa.w, a0); a1 = __fmaf_rn(hv.w, wb.w, a1);
            }
            sal[ew*HEADS + h0] = a0;
            sal[ew*HEADS + h1] = a1;
        }
    }
    __syncthreads();

    // ---- softmax per head (8 threads per head)
    if (t < 64) {
        const int h = t >> 3, sub = t & 7;
        float m = -3.4e38f;
        for (int e = sub; e < EPN; e += 8) m = fmaxf(m, sal[e*HEADS + h]);
#pragma unroll
        for (int o = 1; o < 8; o <<= 1) m = fmaxf(m, __shfl_xor_sync(0xffffffffu, m, o, 8));
        float Z = 0.f;
        for (int e = sub; e < EPN; e += 8) {
            float pp = expf(sal[e*HEADS + h] - m);
            sal[e*HEADS + h] = pp;
            Z += pp;
        }
#pragma unroll
        for (int o = 1; o < 8; o <<= 1) Z += __shfl_xor_sync(0xffffffffu, Z, o, 8);
        float inv = 1.0f / (Z + 1e-9f);
        for (int e = sub; e < EPN; e += 8) sal[e*HEADS + h] *= inv;
    }
    __syncthreads();

    // ---- gather-aggregate from fp16 v (R12-proven form); writes u.p2
    {
        const int d = t & 63, g = t >> 6;
        float acc[LL];
#pragma unroll
        for (int l = 0; l < LL; ++l) acc[l] = 0.f;
        const int h = d >> 3;
        for (int e = g; e < EPN; e += 8) {
            const int e2 = e + 4;
            const bool has2 = (e2 < EPN);
            int s0 = ssrc[e];
            int s1 = has2 ? ssrc[e2] : s0;
            float al0 = sal[e*HEADS + h];
            float al1 = has2 ? sal[e2*HEADS + h] : 0.f;
            const __half2* p0 = g_vh + ((size_t)s0*HV + d)*5;
            const __half2* p1 = g_vh + ((size_t)s1*HV + d)*5;
#pragma unroll
            for (int k = 0; k < 4; ++k) {
                float2 f0 = __half22float2(p0[k]);
                float2 f1 = __half22float2(p1[k]);
                acc[2*k]   = __fmaf_rn(al0, f0.x, __fmaf_rn(al1, f1.x, acc[2*k]));
                acc[2*k+1] = __fmaf_rn(al0, f0.y, __fmaf_rn(al1, f1.y, acc[2*k+1]));
            }
            {
                float2 f0 = __half22float2(p0[4]);
                float2 f1 = __half22float2(p1[4]);
                acc[8] = __fmaf_rn(al0, f0.x, __fmaf_rn(al1, f1.x, acc[8]));
            }
        }
#pragma unroll
        for (int l = 0; l < LL; ++l) u.p2.part[g][l*HV + d] = acc[l];
    }
    __syncthreads();
    for (int idx = t; idx < LL*HV; idx += 256)
        u.p2.agg[idx] = ((u.p2.part[0][idx] + u.p2.part[1][idx]) + u.p2.part[2][idx]) + u.p2.part[3][idx];
    __syncthreads();

    for (int idx = t; idx < LL*BBC; idx += 256) {
        int l = idx >> 5, d = idx & 31;
        const float* w = wo + c_L3[l]*HV*BBC;
        float acc = 0.f;
#pragma unroll 8
        for (int c = 0; c < HV; ++c) acc = __fmaf_rn(u.p2.agg[l*HV + c], w[c*BBC + d], acc);
        if (l == 0) acc += bo[d];
        u.p2.out0[idx] = acc;
    }
    __syncthreads();

    if (t < BBC) {
        float g = 0.f;
        for (int c = 0; c < BBC; ++c) g = __fmaf_rn(u.p2.out0[c], wg[c*BBC + t], g);
        g += bg[t];
        sgate[t] = g * (1.0f / (1.0f + expf(-g)));
    }
    __syncthreads();

    for (int idx = t; idx < LL*BBC; idx += 256) {
        int l = idx >> 5, d = idx & 31;
        const float* w = wf + c_L3[l]*BBC*BBC;
        float acc = 0.f;
#pragma unroll 8
        for (int c = 0; c < BBC; ++c) acc = __fmaf_rn(u.p2.out0[l*BBC + c], w[c*BBC + d], acc);
        if (l == 0) acc += bf[d];
        float val = u.p2.out0[idx] + acc * sgate[d];
        u.p2.outf[idx] = val;
        out[OFF_OUT + (size_t)i*LL*BBC + idx] = val;
    }
    __syncthreads();

    if (t < 3) {
        float acc = 0.f;
        for (int c = 0; c < BBC; ++c) acc = __fmaf_rn(u.p2.outf[(1+t)*BBC + c], wxca[BBC + c], acc);
        svec[t] = acc;
    }
    if (t == 3) {
        float s = 0.f;
        for (int c = 0; c < BBC; ++c) s = __fmaf_rn(u.p2.outf[c], wgate[c], s);
        s += bgate[0];
        sg2 = fmaxf(s, 0.f) + log1pf(expf(-fabsf(s)));
    }
    if (t >= 8 && t < 17) {
        int idx = t - 8;
        int k = idx / 3, m = idx - 3*k;
        float acc = 0.f;
        for (int c = 0; c < BBC; ++c) acc = __fmaf_rn(u.p2.outf[(1+k)*BBC + c], wbb[(BBC + c)*NBB + m], acc);
        subb[idx] = acc;
    }
    __syncthreads();

    const int nz = noise[i];
    if (t < 3)
        out[(size_t)i*3 + t] = X[i*3+t] + (nz ? svec[t]*sg2 : 0.f);
    if (t >= 8 && t < 17) {
        int idx = t - 8;
        int m = idx / 3, k = idx - 3*m;
        out[OFF_BB + (size_t)i*9 + idx] = bbr[(size_t)i*9 + idx] + (nz ? subb[k*3 + m] : 0.f);
    }
}

// ---------------- launch ----------------------------------------------------
extern "C" void kernel_launch(void* const* d_in, const int* in_sizes, int n_in,
                              void* d_out, int out_size)
{
    const float* X      = (const float*)d_in[0];
    const float* bbr    = (const float*)d_in[1];
    const float* bbf    = (const float*)d_in[2];
    const int*   xmask  = (const int*)d_in[4];
    const int*   noise  = (const int*)d_in[5];
    const float* w1     = (const float*)d_in[6];
    const float* b1     = (const float*)d_in[7];
    const float* w2     = (const float*)d_in[8];
    const float* b2     = (const float*)d_in[9];
    const float* wv     = (const float*)d_in[10];
    const float* bv     = (const float*)d_in[11];
    const float* wo     = (const float*)d_in[12];
    const float* bo     = (const float*)d_in[13];
    const float* wg     = (const float*)d_in[14];
    const float* bg     = (const float*)d_in[15];
    const float* wf     = (const float*)d_in[16];
    const float* bf     = (const float*)d_in[17];
    const float* wxca   = (const float*)d_in[18];
    const float* wgate  = (const float*)d_in[20];
    const float* bgate  = (const float*)d_in[21];
    const float* wbb    = (const float*)d_in[22];
    float* out = (float*)d_out;

    node_v_kernel<<<NN/NVB, 512>>>(bbf, bbr, noise, xmask, X, wv, bv, w1, b1);
    row_kernel<<<NN, 256>>>(xmask);
    agg_kernel<<<NN, 256>>>(X, bbr, noise, w1, w2, b2, wo, bo, wg, bg, wf, bf,
                            wxca, wgate, bgate, wbb, out);
}